// round 10
// baseline (speedup 1.0000x reference)
#include <cuda_runtime.h>
#include <cuda_bf16.h>
#include <stdint.h>

// Problem constants
#define BB 64
#define NN 511
#define DD 256
#define MR (BB*NN)   // 32704 rows

// ---------------- scratch (device globals; no allocation allowed) -------------
__device__ float g_H [MR*DD];
__device__ float g_Ek[MR*DD];
__device__ float g_Ev[MR*DD];
__device__ float g_Hq[MR*DD];
__device__ float g_Hk[MR*DD];
__device__ float g_Hv[MR*DD];
__device__ float g_state[BB*DD];
__device__ float g_Sk[BB*DD];
__device__ float g_Sv[BB*DD];
__device__ float g_k2t[DD*DD];      // k2w transposed
// bf16 split operands for tensor-core GEMMs
__device__ __nv_bfloat16 g_Hhi[MR*DD];
__device__ __nv_bfloat16 g_Hlo[MR*DD];
__device__ __nv_bfloat16 g_Ohi[MR*DD];
__device__ __nv_bfloat16 g_Olo[MR*DD];
__device__ __nv_bfloat16 g_Whi[4*DD*DD];   // [q1,k1,v1,o1]
__device__ __nv_bfloat16 g_Wlo[4*DD*DD];

__device__ __forceinline__ void split_bf16(float x, __nv_bfloat16& h, __nv_bfloat16& l){
    h = __float2bfloat16_rn(x);
    l = __float2bfloat16_rn(x - __bfloat162float(h));
}

// ---------------- weight split (4 weights in one launch) ---------------------
__global__ void wsplit_kernel(const float* W0, const float* W1, const float* W2,
                              const float* W3,
                              __nv_bfloat16* __restrict__ hi, __nv_bfloat16* __restrict__ lo){
    int w = blockIdx.y;
    const float* W = (w==0)?W0:((w==1)?W1:((w==2)?W2:W3));
    int i = blockIdx.x*256 + threadIdx.x;
    long o = (long)w*DD*DD + i;
    split_bf16(W[i], hi[o], lo[o]);
}

// ---------------- fp32 transpose (k2w) ---------------------------------------
__global__ void trans_kernel(const float* __restrict__ W, float* __restrict__ Wt){
    __shared__ float t[32][33];
    int bx = blockIdx.x*32, by = blockIdx.y*32;
    int x = threadIdx.x & 31, y0 = threadIdx.x >> 5;
#pragma unroll
    for(int i=0;i<4;i++){ int y=y0*4+i; t[y][x] = W[(by+y)*256 + bx + x]; }
    __syncthreads();
#pragma unroll
    for(int i=0;i<4;i++){ int y=y0*4+i; Wt[(long)(bx+y)*256 + by + x] = t[x][y]; }
}

// ---------------- embedding ---------------------------------------------------
__global__ void embed_kernel(const int* __restrict__ wordid, const int* __restrict__ mask,
                             const float* __restrict__ emb, float* __restrict__ H,
                             __nv_bfloat16* __restrict__ Hhi, __nv_bfloat16* __restrict__ Hlo){
    long node = blockIdx.x;
    int  t    = threadIdx.x;
    int wid = wordid[node];
    int m   = mask[node];
    float v = emb[(long)(wid*m)*DD + t] * (float)m;
    H[node*DD + t] = v;
    split_bf16(v, Hhi[node*DD + t], Hlo[node*DD + t]);
}

// ---------------- state init --------------------------------------------------
__global__ void initstate_kernel(const float* __restrict__ H, float* __restrict__ state){
    int b = blockIdx.x, t = threadIdx.x;
    const float* p = H + (long)b*NN*DD + t;
    float s0=0.f,s1=0.f,s2=0.f,s3=0.f;
    int i = 0;
    for(; i+4 <= NN; i += 4){
        s0 += p[(long)i*DD]; s1 += p[(long)(i+1)*DD];
        s2 += p[(long)(i+2)*DD]; s3 += p[(long)(i+3)*DD];
    }
    for(; i < NN; i++) s0 += p[(long)i*DD];
    state[b*DD + t] = (s0+s1+s2+s3) * (1.f/(float)NN);
}

// ---------------- tensor-core bf16x3 GEMM machinery --------------------------
__device__ __forceinline__ void ldsm4(uint32_t* r, const void* p){
    uint32_t a = (uint32_t)__cvta_generic_to_shared(p);
    asm volatile("ldmatrix.sync.aligned.m8n8.x4.shared.b16 {%0,%1,%2,%3}, [%4];"
        : "=r"(r[0]),"=r"(r[1]),"=r"(r[2]),"=r"(r[3]) : "r"(a));
}
__device__ __forceinline__ void ldsm4t(uint32_t* r, const void* p){
    uint32_t a = (uint32_t)__cvta_generic_to_shared(p);
    asm volatile("ldmatrix.sync.aligned.m8n8.x4.trans.shared.b16 {%0,%1,%2,%3}, [%4];"
        : "=r"(r[0]),"=r"(r[1]),"=r"(r[2]),"=r"(r[3]) : "r"(a));
}
__device__ __forceinline__ void mma16816(float* c, const uint32_t* a, const uint32_t* b){
    asm volatile("mma.sync.aligned.m16n8k16.row.col.f32.bf16.bf16.f32 "
        "{%0,%1,%2,%3}, {%4,%5,%6,%7}, {%8,%9}, {%0,%1,%2,%3};"
        : "+f"(c[0]),"+f"(c[1]),"+f"(c[2]),"+f"(c[3])
        : "r"(a[0]),"r"(a[1]),"r"(a[2]),"r"(a[3]), "r"(b[0]),"r"(b[1]));
}

#define GEMM_PROLOGUE_AND_MAINLOOP() \
    int tid = threadIdx.x, lane = tid & 31, warp = tid >> 5; \
    long bm = (long)blockIdx.x * 64; \
    int wm = warp >> 2, wn = warp & 3; \
    int am = tid >> 2, aseg = (tid & 3) * 8; \
    int bnn = lane * 8; \
    float c[2][8][4]; \
    _Pragma("unroll") for(int i=0;i<2;i++) \
    _Pragma("unroll") for(int j=0;j<8;j++) \
    _Pragma("unroll") for(int k=0;k<4;k++) c[i][j][k]=0.f; \
    uint4 pa0, pa1, pbh[4], pbl[4]; \
    LOADG(0); STORES(); __syncthreads(); \
    int q = lane >> 3, r = lane & 7; \
    int arow = wm*32 + (q&1)*8 + r; \
    int acol = (q>>1)*8; \
    int bkrow = (q&1)*8 + r; \
    int bcol = wn*64 + (q>>1)*8; \
    for(int kt = 0; kt < 8; kt++){ \
        if(kt < 7){ LOADG(kt+1); } \
        _Pragma("unroll") \
        for(int k16 = 0; k16 < 2; k16++){ \
            uint32_t ah[2][4], al[2][4]; \
            _Pragma("unroll") \
            for(int mt=0; mt<2; mt++){ \
                ldsm4(ah[mt], &As[0][arow + mt*16][acol + k16*16]); \
                ldsm4(al[mt], &As[1][arow + mt*16][acol + k16*16]); \
            } \
            uint32_t bh[8][2], bl[8][2]; \
            _Pragma("unroll") \
            for(int p=0; p<4; p++){ \
                uint32_t t4[4]; \
                ldsm4t(t4, &Bs[0][bkrow + k16*16][bcol + p*16]); \
                bh[2*p][0]=t4[0]; bh[2*p][1]=t4[1]; bh[2*p+1][0]=t4[2]; bh[2*p+1][1]=t4[3]; \
                ldsm4t(t4, &Bs[1][bkrow + k16*16][bcol + p*16]); \
                bl[2*p][0]=t4[0]; bl[2*p][1]=t4[1]; bl[2*p+1][0]=t4[2]; bl[2*p+1][1]=t4[3]; \
            } \
            _Pragma("unroll") \
            for(int mt=0; mt<2; mt++) \
            _Pragma("unroll") \
                for(int nt=0; nt<8; nt++){ \
                    mma16816(c[mt][nt], ah[mt], bh[nt]); \
                    mma16816(c[mt][nt], ah[mt], bl[nt]); \
                    mma16816(c[mt][nt], al[mt], bh[nt]); \
                } \
        } \
        __syncthreads(); \
        if(kt < 7){ STORES(); __syncthreads(); } \
    }

#define LOADG(kt) { \
    pa0 = *(const uint4*)(Ahi + (bm+am)*256 + (kt)*32 + aseg); \
    pa1 = *(const uint4*)(Alo + (bm+am)*256 + (kt)*32 + aseg); \
    _Pragma("unroll") \
    for(int j=0;j<4;j++){ \
        long off = ((long)((kt)*32 + warp + 8*j))*256 + bnn; \
        pbh[j] = *(const uint4*)(Bh + off); \
        pbl[j] = *(const uint4*)(Bl + off); } }
#define STORES() { \
    *(uint4*)&As[0][am][aseg] = pa0; \
    *(uint4*)&As[1][am][aseg] = pa1; \
    _Pragma("unroll") \
    for(int j=0;j<4;j++){ \
        *(uint4*)&Bs[0][warp + 8*j][bnn] = pbh[j]; \
        *(uint4*)&Bs[1][warp + 8*j][bnn] = pbl[j]; } }

// ---------- plain GEMM: C = A@W + bias (3-output fused via blockIdx.y) -------
__global__ __launch_bounds__(256,1) void tcgemm3_kernel(
    const __nv_bfloat16* __restrict__ Ahi, const __nv_bfloat16* __restrict__ Alo,
    const __nv_bfloat16* __restrict__ Whi, const __nv_bfloat16* __restrict__ Wlo,
    const float* bias0, const float* bias1, const float* bias2,
    float* C0, float* C1, float* C2, int w0, int w1, int w2)
{
    __shared__ __nv_bfloat16 As[2][64][40];
    __shared__ __nv_bfloat16 Bs[2][32][264];
    int sel = blockIdx.y;
    const float* bias = (sel==0) ? bias0 : ((sel==1) ? bias1 : bias2);
    float*       C    = (sel==0) ? C0    : ((sel==1) ? C1    : C2);
    int          wi   = (sel==0) ? w0    : ((sel==1) ? w1    : w2);
    const __nv_bfloat16* Bh = Whi + (long)wi * (DD*DD);
    const __nv_bfloat16* Bl = Wlo + (long)wi * (DD*DD);

    GEMM_PROLOGUE_AND_MAINLOOP();

    int crow = wm*32 + (lane>>2);
    int ccol = wn*64 + (lane&3)*2;
#pragma unroll
    for(int mt=0; mt<2; mt++)
#pragma unroll
        for(int nt=0; nt<8; nt++){
            long row = bm + crow + mt*16;
            int col = ccol + nt*8;
            float b0v = bias[col], b1v = bias[col+1];
            float2 v0; v0.x = c[mt][nt][0] + b0v; v0.y = c[mt][nt][1] + b1v;
            *(float2*)&C[row*256 + col] = v0;
            float2 v1; v1.x = c[mt][nt][2] + b0v; v1.y = c[mt][nt][3] + b1v;
            *(float2*)&C[(row+8)*256 + col] = v1;
        }
}

// ---------- GEMM + bias + relu + LayerNorm epilogue (for o1 projection) ------
// Writes Y fp32 and bf16 split. Block covers full rows (64x256).
__global__ __launch_bounds__(256,1) void tcgemm_ln_kernel(
    const __nv_bfloat16* __restrict__ Ahi, const __nv_bfloat16* __restrict__ Alo,
    const __nv_bfloat16* __restrict__ Bh, const __nv_bfloat16* __restrict__ Bl,
    const float* __restrict__ bias, const float* __restrict__ gam,
    const float* __restrict__ bet,
    float* __restrict__ Y, __nv_bfloat16* __restrict__ Yhi, __nv_bfloat16* __restrict__ Ylo)
{
    __shared__ __nv_bfloat16 As[2][64][40];
    __shared__ __nv_bfloat16 Bs[2][32][264];
    __shared__ float red1[4][64];
    __shared__ float rowm[64];
    __shared__ float rowi[64];
    __shared__ float gsh[256], bsh[256], bbsh[256];
    gsh[threadIdx.x]  = gam[threadIdx.x];
    bsh[threadIdx.x]  = bet[threadIdx.x];
    bbsh[threadIdx.x] = bias[threadIdx.x];

    GEMM_PROLOGUE_AND_MAINLOOP();

    int crow0 = wm*32 + (lane>>2);
    int ccol = wn*64 + (lane&3)*2;
    // bias + relu in place
#pragma unroll
    for(int mt=0; mt<2; mt++)
#pragma unroll
        for(int nt=0; nt<8; nt++){
            int col = ccol + nt*8;
            c[mt][nt][0] = fmaxf(c[mt][nt][0] + bbsh[col],   0.f);
            c[mt][nt][1] = fmaxf(c[mt][nt][1] + bbsh[col+1], 0.f);
            c[mt][nt][2] = fmaxf(c[mt][nt][2] + bbsh[col],   0.f);
            c[mt][nt][3] = fmaxf(c[mt][nt][3] + bbsh[col+1], 0.f);
        }
    // pass 1: row sums -> mean
#pragma unroll
    for(int mt=0; mt<2; mt++){
        float sA = 0.f, sB = 0.f;
#pragma unroll
        for(int nt=0; nt<8; nt++){
            sA += c[mt][nt][0] + c[mt][nt][1];
            sB += c[mt][nt][2] + c[mt][nt][3];
        }
        sA += __shfl_xor_sync(0xffffffffu, sA, 1); sA += __shfl_xor_sync(0xffffffffu, sA, 2);
        sB += __shfl_xor_sync(0xffffffffu, sB, 1); sB += __shfl_xor_sync(0xffffffffu, sB, 2);
        if((lane&3) == 0){
            int rl = crow0 + mt*16;
            red1[wn][rl]   = sA;
            red1[wn][rl+8] = sB;
        }
    }
    __syncthreads();
    if(tid < 64) rowm[tid] = (red1[0][tid]+red1[1][tid]+red1[2][tid]+red1[3][tid]) * (1.f/256.f);
    __syncthreads();
    // pass 2: sum dx^2 -> inv(sd+eps)
#pragma unroll
    for(int mt=0; mt<2; mt++){
        int rl = crow0 + mt*16;
        float m0 = rowm[rl], m1 = rowm[rl+8];
        float sA = 0.f, sB = 0.f;
#pragma unroll
        for(int nt=0; nt<8; nt++){
            float d0 = c[mt][nt][0]-m0, d1 = c[mt][nt][1]-m0;
            float d2 = c[mt][nt][2]-m1, d3 = c[mt][nt][3]-m1;
            sA += d0*d0 + d1*d1;
            sB += d2*d2 + d3*d3;
        }
        sA += __shfl_xor_sync(0xffffffffu, sA, 1); sA += __shfl_xor_sync(0xffffffffu, sA, 2);
        sB += __shfl_xor_sync(0xffffffffu, sB, 1); sB += __shfl_xor_sync(0xffffffffu, sB, 2);
        if((lane&3) == 0){
            red1[wn][rl]   = sA;
            red1[wn][rl+8] = sB;
        }
    }
    __syncthreads();
    if(tid < 64){
        float var = (red1[0][tid]+red1[1][tid]+red1[2][tid]+red1[3][tid]) * (1.f/255.f);
        rowi[tid] = 1.f / (sqrtf(var) + 1e-6f);
    }
    __syncthreads();
    // write LN'd outputs
#pragma unroll
    for(int mt=0; mt<2; mt++){
        int rl = crow0 + mt*16;
        float m0 = rowm[rl], i0 = rowi[rl];
        float m1 = rowm[rl+8], i1 = rowi[rl+8];
        long row0 = bm + rl, row1 = row0 + 8;
#pragma unroll
        for(int nt=0; nt<8; nt++){
            int col = ccol + nt*8;
            float g0 = gsh[col], g1 = gsh[col+1], be0 = bsh[col], be1 = bsh[col+1];
            float y0 = g0*(c[mt][nt][0]-m0)*i0 + be0;
            float y1 = g1*(c[mt][nt][1]-m0)*i0 + be1;
            float y2 = g0*(c[mt][nt][2]-m1)*i1 + be0;
            float y3 = g1*(c[mt][nt][3]-m1)*i1 + be1;
            float2 f0; f0.x=y0; f0.y=y1;
            *(float2*)&Y[row0*256 + col] = f0;
            float2 f1; f1.x=y2; f1.y=y3;
            *(float2*)&Y[row1*256 + col] = f1;
            __nv_bfloat16 h0,l0,h1,l1;
            split_bf16(y0,h0,l0); split_bf16(y1,h1,l1);
            __nv_bfloat162 ph; ph.x=h0; ph.y=h1;
            __nv_bfloat162 pl; pl.x=l0; pl.y=l1;
            *(__nv_bfloat162*)&Yhi[row0*256 + col] = ph;
            *(__nv_bfloat162*)&Ylo[row0*256 + col] = pl;
            split_bf16(y2,h0,l0); split_bf16(y3,h1,l1);
            ph.x=h0; ph.y=h1; pl.x=l0; pl.y=l1;
            *(__nv_bfloat162*)&Yhi[row1*256 + col] = ph;
            *(__nv_bfloat162*)&Ylo[row1*256 + col] = pl;
        }
    }
}
#undef LOADG
#undef STORES

// ------- fp32 SGEMM for the tiny 64-row state GEMMs (prologue Sk/Sv) --------
__global__ void sgemm_kernel(const float* __restrict__ A, const float* __restrict__ W0,
                             const float* __restrict__ b0v, float* __restrict__ C0v,
                             const float* __restrict__ W1, const float* __restrict__ b1v,
                             float* __restrict__ C1v){
    __shared__ float As[16][68];
    __shared__ float Bs[16][64];
    int tid = threadIdx.x;
    const float* W    = blockIdx.y ? W1  : W0;
    const float* bias = blockIdx.y ? b1v : b0v;
    float*       C    = blockIdx.y ? C1v : C0v;
    int  bn = blockIdx.x * 64;
    int ar = tid >> 2,  ac = (tid & 3)  * 4;
    int br = tid >> 4,  bc = (tid & 15) * 4;
    int tx = tid & 15,  ty = tid >> 4;
    float acc[4][4] = {};
    const float* Ap = A + ar*256 + ac;
    const float* Wp = W + (long)br*256 + bn + bc;
    for(int k0 = 0; k0 < 256; k0 += 16){
        float4 av = *(const float4*)(Ap + k0);
        As[ac+0][ar] = av.x; As[ac+1][ar] = av.y;
        As[ac+2][ar] = av.z; As[ac+3][ar] = av.w;
        *(float4*)&Bs[br][bc] = *(const float4*)(Wp + (long)k0*256);
        __syncthreads();
#pragma unroll
        for(int kk = 0; kk < 16; kk++){
            float a[4], b[4];
#pragma unroll
            for(int i=0;i<4;i++) a[i] = As[kk][ty*4+i];
#pragma unroll
            for(int j=0;j<4;j++) b[j] = Bs[kk][tx*4+j];
#pragma unroll
            for(int i=0;i<4;i++)
#pragma unroll
                for(int j=0;j<4;j++) acc[i][j] += a[i]*b[j];
        }
        __syncthreads();
    }
#pragma unroll
    for(int i=0;i<4;i++){
        long row = ty*4 + i;
        float4 o;
        o.x = acc[i][0] + bias[bn + tx*4 + 0];
        o.y = acc[i][1] + bias[bn + tx*4 + 1];
        o.z = acc[i][2] + bias[bn + tx*4 + 2];
        o.w = acc[i][3] + bias[bn + tx*4 + 3];
        *(float4*)(C + row*256 + bn + tx*4) = o;
    }
}

// ------------- step-1 attention: per node, 5 keys [cl,cr,h,e,s] --------------
__global__ void attn1_kernel(const float* __restrict__ Hq, const float* __restrict__ Hk,
                             const float* __restrict__ Hv,
                             const float* __restrict__ Ek, const float* __restrict__ Ev,
                             const float* __restrict__ Sk, const float* __restrict__ Sv,
                             const float* __restrict__ k1b, const float* __restrict__ v1b,
                             __nv_bfloat16* __restrict__ Ohi, __nv_bfloat16* __restrict__ Olo){
    int  nb   = blockIdx.x;
    int  node = nb % NN;
    int  b    = nb / NN;
    int  t    = threadIdx.x;
    long base = (long)nb * DD;
    bool internal = node < 255;
    long lb = (long)(nb + node + 1) * DD;
    long rb = lb + DD;

    float qv = Hq[base + t];
    float s[5];
    s[0] = qv * (internal ? Hk[lb + t] : k1b[t]);
    s[1] = qv * (internal ? Hk[rb + t] : k1b[t]);
    s[2] = qv * Hk[base + t];
    s[3] = qv * Ek[base + t];
    s[4] = qv * Sk[b*DD + t];
#pragma unroll
    for(int o = 16; o; o >>= 1){
#pragma unroll
        for(int j=0;j<5;j++) s[j] += __shfl_xor_sync(0xffffffffu, s[j], o);
    }
    const float scale = 0.17677669529663687f;
    float mx = -1e30f;
#pragma unroll
    for(int j=0;j<5;j++){ s[j] *= scale; mx = fmaxf(mx, s[j]); }
    float w[5], sum = 0.f;
#pragma unroll
    for(int j=0;j<5;j++){ w[j] = __expf(s[j]-mx); sum += w[j]; }
    float inv = 1.f / sum;
    float v0 = internal ? Hv[lb + t] : v1b[t];
    float v1 = internal ? Hv[rb + t] : v1b[t];
    float v2 = Hv[base + t];
    float v3 = Ev[base + t];
    float v4 = Sv[b*DD + t];
    float ov = (w[0]*v0 + w[1]*v1 + w[2]*v2 + w[3]*v3 + w[4]*v4) * inv;
    split_bf16(ov, Ohi[base + t], Olo[base + t]);
}

// ======= step-2 mega kernel: q2proj -> scores -> softmax -> mix -> v2/o2 =====
// ======= -> relu+LN -> new state -> next-iter Sk/Sv projections ==============
__global__ void step2_kernel(const float* __restrict__ H, float* __restrict__ state,
    const float* __restrict__ q2w, const float* __restrict__ q2b,
    const float* __restrict__ k2t,
    const float* __restrict__ v2w, const float* __restrict__ v2b,
    const float* __restrict__ o2w, const float* __restrict__ o2b,
    const float* __restrict__ ln2g, const float* __restrict__ ln2b,
    const float* __restrict__ k1w, const float* __restrict__ k1b,
    const float* __restrict__ v1w, const float* __restrict__ v1b,
    float* __restrict__ Sk, float* __restrict__ Sv)
{
    int b = blockIdx.x, t = threadIdx.x, warp = t >> 5, lane = t & 31;
    __shared__ float st[256];
    __shared__ float q2f[256];
    __shared__ float qts[8][256];
    __shared__ float scs[8][NN];
    __shared__ float hb[8][256];
    __shared__ float o2s[256];
    __shared__ float ys[256];
    __shared__ float wsh[8];
    __shared__ float stat[2];

    st[t] = state[b*DD + t];
    __syncthreads();
    // q2 = state@q2w + q2b
    {
        float a = 0.f;
        for(int k = 0; k < 256; k++) a += st[k] * q2w[(long)k*256 + t];
        q2f[t] = a + q2b[t];
    }
    __syncthreads();
    // folded queries qt[h] = k2w[:,hcols]^T @ q2[hcols]   (k2b dropped: uniform)
#pragma unroll
    for(int hh = 0; hh < 8; hh++){
        float s = 0.f;
#pragma unroll
        for(int d = 0; d < 32; d++) s += k2t[(long)(hh*32+d)*256 + t] * q2f[hh*32+d];
        qts[hh][t] = s;
    }
    __syncthreads();
    // scores over the 511 h rows
    const float scale = 0.17677669529663687f;
    for(int i = warp; i < NN; i += 8){
        const float* hp = H + ((long)b*NN + i)*DD;
        float hv[8];
#pragma unroll
        for(int j=0;j<8;j++) hv[j] = hp[lane + 32*j];
#pragma unroll
        for(int hh=0; hh<8; hh++){
            float s = 0.f;
#pragma unroll
            for(int j=0;j<8;j++) s += hv[j]*qts[hh][lane + 32*j];
#pragma unroll
            for(int o=16;o;o>>=1) s += __shfl_xor_sync(0xffffffffu, s, o);
            if(lane == 0) scs[hh][i] = s * scale;
        }
    }
    __syncthreads();
    // softmax per head (warp == head)
    {
        float* sp = scs[warp];
        float mx = -1e30f;
        for(int i = lane; i < NN; i += 32) mx = fmaxf(mx, sp[i]);
#pragma unroll
        for(int o=16;o;o>>=1) mx = fmaxf(mx, __shfl_xor_sync(0xffffffffu, mx, o));
        float sum = 0.f;
        for(int i = lane; i < NN; i += 32){ float w = __expf(sp[i]-mx); sp[i] = w; sum += w; }
#pragma unroll
        for(int o=16;o;o>>=1) sum += __shfl_xor_sync(0xffffffffu, sum, o);
        float inv = 1.f/sum;
        for(int i = lane; i < NN; i += 32) sp[i] *= inv;
    }
    __syncthreads();
    // mix: hbar[h,:] = sum_i a[h,i] * H[b,i,:]
    {
        float acc[8] = {};
        const float* hp = H + (long)b*NN*DD + t;
        for(int i = 0; i < NN; i++){
            float hval = hp[(long)i*DD];
#pragma unroll
            for(int hh=0; hh<8; hh++) acc[hh] += scs[hh][i]*hval;
        }
#pragma unroll
        for(int hh=0; hh<8; hh++) hb[hh][t] = acc[hh];
    }
    __syncthreads();
    // v2 projection of mixed vector (+ v2b)
    {
        int hh = t >> 5;
        float s = 0.f;
        for(int k = 0; k < 256; k++) s += hb[hh][k] * v2w[(long)k*256 + t];
        o2s[t] = s + v2b[t];
    }
    __syncthreads();
    // o2 projection + relu + LayerNorm -> new state
    {
        float s = 0.f;
        for(int k = 0; k < 256; k++) s += o2s[k] * o2w[(long)k*256 + t];
        float u = fmaxf(s + o2b[t], 0.f);
        float v = u;
#pragma unroll
        for(int o=16;o;o>>=1) v += __shfl_xor_sync(0xffffffffu, v, o);
        if(lane==0) wsh[warp] = v;
        __syncthreads();
        if(t < 32){
            float r = (t < 8) ? wsh[t] : 0.f;
#pragma unroll
            for(int o=4;o;o>>=1) r += __shfl_xor_sync(0xffffffffu, r, o);
            if(t==0) stat[0] = r;
        }
        __syncthreads();
        float mean = stat[0] * (1.f/256.f);
        float dx = u - mean;
        v = dx*dx;
#pragma unroll
        for(int o=16;o;o>>=1) v += __shfl_xor_sync(0xffffffffu, v, o);
        if(lane==0) wsh[warp] = v;
        __syncthreads();
        if(t < 32){
            float r = (t < 8) ? wsh[t] : 0.f;
#pragma unroll
            for(int o=4;o;o>>=1) r += __shfl_xor_sync(0xffffffffu, r, o);
            if(t==0) stat[1] = r;
        }
        __syncthreads();
        float sd = sqrtf(stat[1] * (1.f/255.f));
        float y = ln2g[t]*dx/(sd + 1e-6f) + ln2b[t];
        state[b*DD + t] = y;
        ys[t] = y;
    }
    __syncthreads();
    // pre-project next iteration's Sk/Sv
    {
        float sk = 0.f, sv = 0.f;
        for(int k = 0; k < 256; k++){
            float yv = ys[k];
            sk += yv * k1w[(long)k*256 + t];
            sv += yv * v1w[(long)k*256 + t];
        }
        Sk[b*DD + t] = sk + k1b[t];
        Sv[b*DD + t] = sv + v1b[t];
    }
}

// ------------- final: logits = H @ linw[256,5] + linb ------------------------
__global__ void logits_kernel(const float* __restrict__ H, const float* __restrict__ linw,
                              const float* __restrict__ linb, float* __restrict__ out){
    __shared__ float w[DD*5];
    int t = threadIdx.x;
    for(int i = t; i < DD*5; i += 256) w[i] = linw[i];
    __syncthreads();
    int warp = t >> 5, lane = t & 31;
    long row = (long)blockIdx.x*8 + warp;
    const float* hp = H + row*DD;
    float hr[8];
#pragma unroll
    for(int k=0;k<8;k++) hr[k] = hp[lane + 32*k];
#pragma unroll
    for(int c=0;c<5;c++){
        float a = 0.f;
#pragma unroll
        for(int k=0;k<8;k++) a += hr[k] * w[(lane+32*k)*5 + c];
#pragma unroll
        for(int o=16;o;o>>=1) a += __shfl_xor_sync(0xffffffffu, a, o);
        if(lane==0) out[row*5 + c] = a + linb[c];
    }
}

// ------------------------------- host side -----------------------------------
extern "C" void kernel_launch(void* const* d_in, const int* in_sizes, int n_in,
                              void* d_out, int out_size){
    const int*   wordid = (const int*)  d_in[0];
    const int*   mask   = (const int*)  d_in[1];
    const float* emb    = (const float*)d_in[2];
    const float* q1w=(const float*)d_in[3],  *q1b=(const float*)d_in[4];
    const float* k1w=(const float*)d_in[5],  *k1b=(const float*)d_in[6];
    const float* v1w=(const float*)d_in[7],  *v1b=(const float*)d_in[8];
    const float* o1w=(const float*)d_in[9],  *o1b=(const float*)d_in[10];
    const float* q2w=(const float*)d_in[11], *q2b=(const float*)d_in[12];
    const float* k2w=(const float*)d_in[13], *k2b=(const float*)d_in[14];
    const float* v2w=(const float*)d_in[15], *v2b=(const float*)d_in[16];
    const float* o2w=(const float*)d_in[17], *o2b=(const float*)d_in[18];
    const float* ln1g=(const float*)d_in[19],*ln1bb=(const float*)d_in[20];
    const float* ln2g=(const float*)d_in[21],*ln2bb=(const float*)d_in[22];
    const float* linw=(const float*)d_in[23],*linb=(const float*)d_in[24];
    float* out = (float*)d_out;
    (void)k2b;  // uniform score shift -> softmax invariant

    float *H,*Ek,*Ev,*Hq,*Hk,*Hv,*state,*Sk,*Sv,*k2t;
    __nv_bfloat16 *Hhi,*Hlo,*Ohi,*Olo,*Whi,*Wlo;
    cudaGetSymbolAddress((void**)&H,  g_H);
    cudaGetSymbolAddress((void**)&Ek, g_Ek);
    cudaGetSymbolAddress((void**)&Ev, g_Ev);
    cudaGetSymbolAddress((void**)&Hq, g_Hq);
    cudaGetSymbolAddress((void**)&Hk, g_Hk);
    cudaGetSymbolAddress((void**)&Hv, g_Hv);
    cudaGetSymbolAddress((void**)&state, g_state);
    cudaGetSymbolAddress((void**)&Sk, g_Sk);
    cudaGetSymbolAddress((void**)&Sv, g_Sv);
    cudaGetSymbolAddress((void**)&k2t, g_k2t);
    cudaGetSymbolAddress((void**)&Hhi, g_Hhi);
    cudaGetSymbolAddress((void**)&Hlo, g_Hlo);
    cudaGetSymbolAddress((void**)&Ohi, g_Ohi);
    cudaGetSymbolAddress((void**)&Olo, g_Olo);
    cudaGetSymbolAddress((void**)&Whi, g_Whi);
    cudaGetSymbolAddress((void**)&Wlo, g_Wlo);

    int mt = MR/64;  // 511

    wsplit_kernel<<<dim3(DD*DD/256, 4), 256>>>(q1w, k1w, v1w, o1w, Whi, Wlo);
    trans_kernel <<<dim3(8,8), 256>>>(k2w, k2t);
    embed_kernel    <<<MR, 256>>>(wordid, mask, emb, H, Hhi, Hlo);
    initstate_kernel<<<BB, 256>>>(H, state);
    sgemm_kernel<<<dim3(4,2), 256>>>(state, k1w, k1b, Sk, v1w, v1b, Sv);

    for(int it = 0; it < 5; it++){
        // iter 0: h == e, so k1/v1 projections double as the loop-invariant Ek/Ev
        float* kOut = (it == 0) ? Ek : Hk;
        float* vOut = (it == 0) ? Ev : Hv;
        tcgemm3_kernel<<<dim3(mt,3), 256>>>(Hhi, Hlo, Whi, Wlo,
                                            q1b, k1b, v1b, Hq, kOut, vOut, 0, 1, 2);
        attn1_kernel<<<MR, 256>>>(Hq, kOut, vOut, Ek, Ev, Sk, Sv, k1b, v1b, Ohi, Olo);
        tcgemm_ln_kernel<<<mt, 256>>>(Ohi, Olo, Whi + 3L*DD*DD, Wlo + 3L*DD*DD,
                                      o1b, ln1g, ln1bb, H, Hhi, Hlo);
        step2_kernel<<<BB, 256>>>(H, state, q2w, q2b, k2t, v2w, v2b, o2w, o2b,
                                  ln2g, ln2bb, k1w, k1b, v1w, v1b, Sk, Sv);
    }

    logits_kernel<<<MR/8, 256>>>(H, linw, linb, out);
}

// round 11
// speedup vs baseline: 1.5075x; 1.5075x over previous
#include <cuda_runtime.h>
#include <cuda_bf16.h>
#include <stdint.h>

// Problem constants
#define BB 64
#define NN 511
#define DD 256
#define MR (BB*NN)   // 32704 rows
#define MT (MR/64)   // 511 M tiles

// ---------------- scratch (device globals; no allocation allowed) -------------
__device__ float g_H [MR*DD];
__device__ float g_Ek[MR*DD];
__device__ float g_Ev[MR*DD];
__device__ float g_Hq[MR*DD];
__device__ float g_Hk[MR*DD];
__device__ float g_Hv[MR*DD];
__device__ float g_state[BB*DD];
__device__ float g_Sk[BB*DD];
__device__ float g_Sv[BB*DD];
__device__ float g_k2t[DD*DD];      // k2w transposed
// bf16 split operands for tensor-core GEMMs
__device__ __nv_bfloat16 g_Hhi[MR*DD];
__device__ __nv_bfloat16 g_Hlo[MR*DD];
__device__ __nv_bfloat16 g_Ohi[MR*DD];
__device__ __nv_bfloat16 g_Olo[MR*DD];
__device__ __nv_bfloat16 g_Whi[4*DD*DD];   // [q1,k1,v1,o1]
__device__ __nv_bfloat16 g_Wlo[4*DD*DD];

__device__ __forceinline__ void split_bf16(float x, __nv_bfloat16& h, __nv_bfloat16& l){
    h = __float2bfloat16_rn(x);
    l = __float2bfloat16_rn(x - __bfloat162float(h));
}

// ---------------- weight split (4 weights in one launch) ---------------------
__global__ void wsplit_kernel(const float* W0, const float* W1, const float* W2,
                              const float* W3,
                              __nv_bfloat16* __restrict__ hi, __nv_bfloat16* __restrict__ lo){
    int w = blockIdx.y;
    const float* W = (w==0)?W0:((w==1)?W1:((w==2)?W2:W3));
    int i = blockIdx.x*256 + threadIdx.x;
    long o = (long)w*DD*DD + i;
    split_bf16(W[i], hi[o], lo[o]);
}

// ---------------- fp32 transpose (k2w) ---------------------------------------
__global__ void trans_kernel(const float* __restrict__ W, float* __restrict__ Wt){
    __shared__ float t[32][33];
    int bx = blockIdx.x*32, by = blockIdx.y*32;
    int x = threadIdx.x & 31, y0 = threadIdx.x >> 5;
#pragma unroll
    for(int i=0;i<4;i++){ int y=y0*4+i; t[y][x] = W[(by+y)*256 + bx + x]; }
    __syncthreads();
#pragma unroll
    for(int i=0;i<4;i++){ int y=y0*4+i; Wt[(long)(bx+y)*256 + by + x] = t[x][y]; }
}

// ---------------- embedding ---------------------------------------------------
__global__ void embed_kernel(const int* __restrict__ wordid, const int* __restrict__ mask,
                             const float* __restrict__ emb, float* __restrict__ H,
                             __nv_bfloat16* __restrict__ Hhi, __nv_bfloat16* __restrict__ Hlo){
    long node = blockIdx.x;
    int  t    = threadIdx.x;
    int wid = wordid[node];
    int m   = mask[node];
    float v = emb[(long)(wid*m)*DD + t] * (float)m;
    H[node*DD + t] = v;
    split_bf16(v, Hhi[node*DD + t], Hlo[node*DD + t]);
}

// ---------------- state init --------------------------------------------------
__global__ void initstate_kernel(const float* __restrict__ H, float* __restrict__ state){
    int b = blockIdx.x, t = threadIdx.x;
    const float* p = H + (long)b*NN*DD + t;
    float s0=0.f,s1=0.f,s2=0.f,s3=0.f;
    int i = 0;
    for(; i+4 <= NN; i += 4){
        s0 += p[(long)i*DD]; s1 += p[(long)(i+1)*DD];
        s2 += p[(long)(i+2)*DD]; s3 += p[(long)(i+3)*DD];
    }
    for(; i < NN; i++) s0 += p[(long)i*DD];
    state[b*DD + t] = (s0+s1+s2+s3) * (1.f/(float)NN);
}

// ---------------- tensor-core bf16x3 GEMM core --------------------------------
__device__ __forceinline__ void ldsm4(uint32_t* r, const void* p){
    uint32_t a = (uint32_t)__cvta_generic_to_shared(p);
    asm volatile("ldmatrix.sync.aligned.m8n8.x4.shared.b16 {%0,%1,%2,%3}, [%4];"
        : "=r"(r[0]),"=r"(r[1]),"=r"(r[2]),"=r"(r[3]) : "r"(a));
}
__device__ __forceinline__ void ldsm4t(uint32_t* r, const void* p){
    uint32_t a = (uint32_t)__cvta_generic_to_shared(p);
    asm volatile("ldmatrix.sync.aligned.m8n8.x4.trans.shared.b16 {%0,%1,%2,%3}, [%4];"
        : "=r"(r[0]),"=r"(r[1]),"=r"(r[2]),"=r"(r[3]) : "r"(a));
}
__device__ __forceinline__ void mma16816(float* c, const uint32_t* a, const uint32_t* b){
    asm volatile("mma.sync.aligned.m16n8k16.row.col.f32.bf16.bf16.f32 "
        "{%0,%1,%2,%3}, {%4,%5,%6,%7}, {%8,%9}, {%0,%1,%2,%3};"
        : "+f"(c[0]),"+f"(c[1]),"+f"(c[2]),"+f"(c[3])
        : "r"(a[0]),"r"(a[1]),"r"(a[2]),"r"(a[3]), "r"(b[0]),"r"(b[1]));
}

struct SmemQ {
    __nv_bfloat16 As[2][64][40];
    __nv_bfloat16 Bs[2][32][264];
};
struct SmemS {
    float st[256], q2f[256], qts[8][256], scs[8][NN], hb[8][256];
    float o2s[256], ys[256], wsh[8], stat[2];
};
union SmemU { SmemQ q; SmemS s; };

__device__ __forceinline__ void gemm_core(SmemQ& sq,
    const __nv_bfloat16* __restrict__ Ahi, const __nv_bfloat16* __restrict__ Alo,
    const __nv_bfloat16* __restrict__ Bh, const __nv_bfloat16* __restrict__ Bl,
    long bm, float c[2][8][4])
{
    int tid = threadIdx.x, lane = tid & 31, warp = tid >> 5;
    int wm = warp >> 2, wn = warp & 3;
    int am = tid >> 2, aseg = (tid & 3) * 8;
    int bnn = lane * 8;
#pragma unroll
    for(int i=0;i<2;i++)
#pragma unroll
        for(int j=0;j<8;j++)
#pragma unroll
            for(int k=0;k<4;k++) c[i][j][k]=0.f;
    uint4 pa0, pa1, pbh[4], pbl[4];
#define GLOAD(kt) { \
    pa0 = *(const uint4*)(Ahi + (bm+am)*256 + (kt)*32 + aseg); \
    pa1 = *(const uint4*)(Alo + (bm+am)*256 + (kt)*32 + aseg); \
    _Pragma("unroll") \
    for(int j=0;j<4;j++){ \
        long off = ((long)((kt)*32 + warp + 8*j))*256 + bnn; \
        pbh[j] = *(const uint4*)(Bh + off); \
        pbl[j] = *(const uint4*)(Bl + off); } }
#define GSTORE() { \
    *(uint4*)&sq.As[0][am][aseg] = pa0; \
    *(uint4*)&sq.As[1][am][aseg] = pa1; \
    _Pragma("unroll") \
    for(int j=0;j<4;j++){ \
        *(uint4*)&sq.Bs[0][warp + 8*j][bnn] = pbh[j]; \
        *(uint4*)&sq.Bs[1][warp + 8*j][bnn] = pbl[j]; } }

    GLOAD(0); GSTORE(); __syncthreads();

    int q = lane >> 3, r = lane & 7;
    int arow = wm*32 + (q&1)*8 + r;
    int acol = (q>>1)*8;
    int bkrow = (q&1)*8 + r;
    int bcol = wn*64 + (q>>1)*8;

    for(int kt = 0; kt < 8; kt++){
        if(kt < 7){ GLOAD(kt+1); }
#pragma unroll
        for(int k16 = 0; k16 < 2; k16++){
            uint32_t ah[2][4], al[2][4];
#pragma unroll
            for(int mt=0; mt<2; mt++){
                ldsm4(ah[mt], &sq.As[0][arow + mt*16][acol + k16*16]);
                ldsm4(al[mt], &sq.As[1][arow + mt*16][acol + k16*16]);
            }
            uint32_t bh[8][2], bl[8][2];
#pragma unroll
            for(int p=0; p<4; p++){
                uint32_t t4[4];
                ldsm4t(t4, &sq.Bs[0][bkrow + k16*16][bcol + p*16]);
                bh[2*p][0]=t4[0]; bh[2*p][1]=t4[1]; bh[2*p+1][0]=t4[2]; bh[2*p+1][1]=t4[3];
                ldsm4t(t4, &sq.Bs[1][bkrow + k16*16][bcol + p*16]);
                bl[2*p][0]=t4[0]; bl[2*p][1]=t4[1]; bl[2*p+1][0]=t4[2]; bl[2*p+1][1]=t4[3];
            }
#pragma unroll
            for(int mt=0; mt<2; mt++)
#pragma unroll
                for(int nt=0; nt<8; nt++){
                    mma16816(c[mt][nt], ah[mt], bh[nt]);
                    mma16816(c[mt][nt], ah[mt], bl[nt]);
                    mma16816(c[mt][nt], al[mt], bh[nt]);
                }
        }
        __syncthreads();
        if(kt < 7){ GSTORE(); __syncthreads(); }
    }
#undef GLOAD
#undef GSTORE
}

// ---------- plain GEMM epilogue -----------------------------------------------
__device__ __forceinline__ void gemm_store(float c[2][8][4], const float* bias,
                                           float* C, long bm){
    int tid = threadIdx.x, lane = tid & 31, warp = tid >> 5;
    int wm = warp >> 2, wn = warp & 3;
    int crow = wm*32 + (lane>>2);
    int ccol = wn*64 + (lane&3)*2;
#pragma unroll
    for(int mt=0; mt<2; mt++)
#pragma unroll
        for(int nt=0; nt<8; nt++){
            long row = bm + crow + mt*16;
            int col = ccol + nt*8;
            float b0v = bias[col], b1v = bias[col+1];
            float2 v0; v0.x = c[mt][nt][0] + b0v; v0.y = c[mt][nt][1] + b1v;
            *(float2*)&C[row*256 + col] = v0;
            float2 v1; v1.x = c[mt][nt][2] + b0v; v1.y = c[mt][nt][3] + b1v;
            *(float2*)&C[(row+8)*256 + col] = v1;
        }
}

// ---------- standalone 3-output GEMM (prologue qkv_0) -------------------------
__global__ __launch_bounds__(256,1) void tcgemm3_kernel(
    const __nv_bfloat16* __restrict__ Ahi, const __nv_bfloat16* __restrict__ Alo,
    const __nv_bfloat16* __restrict__ Whi, const __nv_bfloat16* __restrict__ Wlo,
    const float* bias0, const float* bias1, const float* bias2,
    float* C0, float* C1, float* C2)
{
    __shared__ SmemQ sq;
    int sel = blockIdx.y;
    const float* bias = (sel==0) ? bias0 : ((sel==1) ? bias1 : bias2);
    float*       C    = (sel==0) ? C0    : ((sel==1) ? C1    : C2);
    const __nv_bfloat16* Bh = Whi + (long)sel * (DD*DD);
    const __nv_bfloat16* Bl = Wlo + (long)sel * (DD*DD);
    long bm = (long)blockIdx.x * 64;
    float c[2][8][4];
    gemm_core(sq, Ahi, Alo, Bh, Bl, bm, c);
    gemm_store(c, bias, C, bm);
}

// ---------- GEMM + bias + relu + LayerNorm epilogue (o1 projection) -----------
__global__ __launch_bounds__(256,1) void tcgemm_ln_kernel(
    const __nv_bfloat16* __restrict__ Ahi, const __nv_bfloat16* __restrict__ Alo,
    const __nv_bfloat16* __restrict__ Bh, const __nv_bfloat16* __restrict__ Bl,
    const float* __restrict__ bias, const float* __restrict__ gam,
    const float* __restrict__ bet,
    float* __restrict__ Y, __nv_bfloat16* __restrict__ Yhi, __nv_bfloat16* __restrict__ Ylo)
{
    __shared__ SmemQ sq;
    __shared__ float red1[4][64];
    __shared__ float rowm[64];
    __shared__ float rowi[64];
    __shared__ float gsh[256], bsh[256], bbsh[256];
    gsh[threadIdx.x]  = gam[threadIdx.x];
    bsh[threadIdx.x]  = bet[threadIdx.x];
    bbsh[threadIdx.x] = bias[threadIdx.x];
    long bm = (long)blockIdx.x * 64;
    float c[2][8][4];
    gemm_core(sq, Ahi, Alo, Bh, Bl, bm, c);

    int tid = threadIdx.x, lane = tid & 31, warp = tid >> 5;
    int wm = warp >> 2, wn = warp & 3;
    int crow0 = wm*32 + (lane>>2);
    int ccol = wn*64 + (lane&3)*2;
#pragma unroll
    for(int mt=0; mt<2; mt++)
#pragma unroll
        for(int nt=0; nt<8; nt++){
            int col = ccol + nt*8;
            c[mt][nt][0] = fmaxf(c[mt][nt][0] + bbsh[col],   0.f);
            c[mt][nt][1] = fmaxf(c[mt][nt][1] + bbsh[col+1], 0.f);
            c[mt][nt][2] = fmaxf(c[mt][nt][2] + bbsh[col],   0.f);
            c[mt][nt][3] = fmaxf(c[mt][nt][3] + bbsh[col+1], 0.f);
        }
#pragma unroll
    for(int mt=0; mt<2; mt++){
        float sA = 0.f, sB = 0.f;
#pragma unroll
        for(int nt=0; nt<8; nt++){
            sA += c[mt][nt][0] + c[mt][nt][1];
            sB += c[mt][nt][2] + c[mt][nt][3];
        }
        sA += __shfl_xor_sync(0xffffffffu, sA, 1); sA += __shfl_xor_sync(0xffffffffu, sA, 2);
        sB += __shfl_xor_sync(0xffffffffu, sB, 1); sB += __shfl_xor_sync(0xffffffffu, sB, 2);
        if((lane&3) == 0){
            int rl = crow0 + mt*16;
            red1[wn][rl]   = sA;
            red1[wn][rl+8] = sB;
        }
    }
    __syncthreads();
    if(tid < 64) rowm[tid] = (red1[0][tid]+red1[1][tid]+red1[2][tid]+red1[3][tid]) * (1.f/256.f);
    __syncthreads();
#pragma unroll
    for(int mt=0; mt<2; mt++){
        int rl = crow0 + mt*16;
        float m0 = rowm[rl], m1 = rowm[rl+8];
        float sA = 0.f, sB = 0.f;
#pragma unroll
        for(int nt=0; nt<8; nt++){
            float d0 = c[mt][nt][0]-m0, d1 = c[mt][nt][1]-m0;
            float d2 = c[mt][nt][2]-m1, d3 = c[mt][nt][3]-m1;
            sA += d0*d0 + d1*d1;
            sB += d2*d2 + d3*d3;
        }
        sA += __shfl_xor_sync(0xffffffffu, sA, 1); sA += __shfl_xor_sync(0xffffffffu, sA, 2);
        sB += __shfl_xor_sync(0xffffffffu, sB, 1); sB += __shfl_xor_sync(0xffffffffu, sB, 2);
        if((lane&3) == 0){
            red1[wn][rl]   = sA;
            red1[wn][rl+8] = sB;
        }
    }
    __syncthreads();
    if(tid < 64){
        float var = (red1[0][tid]+red1[1][tid]+red1[2][tid]+red1[3][tid]) * (1.f/255.f);
        rowi[tid] = 1.f / (sqrtf(var) + 1e-6f);
    }
    __syncthreads();
#pragma unroll
    for(int mt=0; mt<2; mt++){
        int rl = crow0 + mt*16;
        float m0 = rowm[rl], i0 = rowi[rl];
        float m1 = rowm[rl+8], i1 = rowi[rl+8];
        long row0 = bm + rl, row1 = row0 + 8;
#pragma unroll
        for(int nt=0; nt<8; nt++){
            int col = ccol + nt*8;
            float g0 = gsh[col], g1 = gsh[col+1], be0 = bsh[col], be1 = bsh[col+1];
            float y0 = g0*(c[mt][nt][0]-m0)*i0 + be0;
            float y1 = g1*(c[mt][nt][1]-m0)*i0 + be1;
            float y2 = g0*(c[mt][nt][2]-m1)*i1 + be0;
            float y3 = g1*(c[mt][nt][3]-m1)*i1 + be1;
            float2 f0; f0.x=y0; f0.y=y1;
            *(float2*)&Y[row0*256 + col] = f0;
            float2 f1; f1.x=y2; f1.y=y3;
            *(float2*)&Y[row1*256 + col] = f1;
            __nv_bfloat16 h0,l0,h1,l1;
            split_bf16(y0,h0,l0); split_bf16(y1,h1,l1);
            __nv_bfloat162 ph; ph.x=h0; ph.y=h1;
            __nv_bfloat162 pl; pl.x=l0; pl.y=l1;
            *(__nv_bfloat162*)&Yhi[row0*256 + col] = ph;
            *(__nv_bfloat162*)&Ylo[row0*256 + col] = pl;
            split_bf16(y2,h0,l0); split_bf16(y3,h1,l1);
            ph.x=h0; ph.y=h1; pl.x=l0; pl.y=l1;
            *(__nv_bfloat162*)&Yhi[row1*256 + col] = ph;
            *(__nv_bfloat162*)&Ylo[row1*256 + col] = pl;
        }
    }
}

// ------- fp32 SGEMM for the tiny 64-row state GEMMs (prologue Sk/Sv) ---------
__global__ void sgemm_kernel(const float* __restrict__ A, const float* __restrict__ W0,
                             const float* __restrict__ b0v, float* __restrict__ C0v,
                             const float* __restrict__ W1, const float* __restrict__ b1v,
                             float* __restrict__ C1v){
    __shared__ float As[16][68];
    __shared__ float Bs[16][64];
    int tid = threadIdx.x;
    const float* W    = blockIdx.y ? W1  : W0;
    const float* bias = blockIdx.y ? b1v : b0v;
    float*       C    = blockIdx.y ? C1v : C0v;
    int  bn = blockIdx.x * 64;
    int ar = tid >> 2,  ac = (tid & 3)  * 4;
    int br = tid >> 4,  bc = (tid & 15) * 4;
    int tx = tid & 15,  ty = tid >> 4;
    float acc[4][4] = {};
    const float* Ap = A + ar*256 + ac;
    const float* Wp = W + (long)br*256 + bn + bc;
    for(int k0 = 0; k0 < 256; k0 += 16){
        float4 av = *(const float4*)(Ap + k0);
        As[ac+0][ar] = av.x; As[ac+1][ar] = av.y;
        As[ac+2][ar] = av.z; As[ac+3][ar] = av.w;
        *(float4*)&Bs[br][bc] = *(const float4*)(Wp + (long)k0*256);
        __syncthreads();
#pragma unroll
        for(int kk = 0; kk < 16; kk++){
            float a[4], b[4];
#pragma unroll
            for(int i=0;i<4;i++) a[i] = As[kk][ty*4+i];
#pragma unroll
            for(int j=0;j<4;j++) b[j] = Bs[kk][tx*4+j];
#pragma unroll
            for(int i=0;i<4;i++)
#pragma unroll
                for(int j=0;j<4;j++) acc[i][j] += a[i]*b[j];
        }
        __syncthreads();
    }
#pragma unroll
    for(int i=0;i<4;i++){
        long row = ty*4 + i;
        float4 o;
        o.x = acc[i][0] + bias[bn + tx*4 + 0];
        o.y = acc[i][1] + bias[bn + tx*4 + 1];
        o.z = acc[i][2] + bias[bn + tx*4 + 2];
        o.w = acc[i][3] + bias[bn + tx*4 + 3];
        *(float4*)(C + row*256 + bn + tx*4) = o;
    }
}

// ------------- step-1 attention, float4 / 64-threads-per-node ----------------
__global__ void attn1_kernel(const float* __restrict__ Hq, const float* __restrict__ Hk,
                             const float* __restrict__ Hv,
                             const float* __restrict__ Ek, const float* __restrict__ Ev,
                             const float* __restrict__ Sk, const float* __restrict__ Sv,
                             const float* __restrict__ k1b, const float* __restrict__ v1b,
                             __nv_bfloat16* __restrict__ Ohi, __nv_bfloat16* __restrict__ Olo){
    int tid = threadIdx.x;
    int nb  = blockIdx.x*4 + (tid>>6);   // 4 nodes per block
    int g   = tid & 63;                  // 64 threads per node, float4 each
    int node = nb % NN;
    int b    = nb / NN;
    long base = (long)nb*DD + 4*g;
    bool internal = node < 255;
    long lb = internal ? ((long)(nb + node + 1)*DD + 4*g) : base;
    long rb = internal ? (lb + DD) : base;

    float4 qv  = *(const float4*)(Hq + base);
    float4 kb4 = *(const float4*)(k1b + 4*g);
    float4 k0 = internal ? *(const float4*)(Hk + lb) : kb4;
    float4 k1 = internal ? *(const float4*)(Hk + rb) : kb4;
    float4 k2 = *(const float4*)(Hk + base);
    float4 k3 = *(const float4*)(Ek + base);
    float4 k4 = *(const float4*)(Sk + b*DD + 4*g);

    float s[5];
    s[0] = qv.x*k0.x + qv.y*k0.y + qv.z*k0.z + qv.w*k0.w;
    s[1] = qv.x*k1.x + qv.y*k1.y + qv.z*k1.z + qv.w*k1.w;
    s[2] = qv.x*k2.x + qv.y*k2.y + qv.z*k2.z + qv.w*k2.w;
    s[3] = qv.x*k3.x + qv.y*k3.y + qv.z*k3.z + qv.w*k3.w;
    s[4] = qv.x*k4.x + qv.y*k4.y + qv.z*k4.z + qv.w*k4.w;
#pragma unroll
    for(int o = 4; o; o >>= 1){
#pragma unroll
        for(int j=0;j<5;j++) s[j] += __shfl_xor_sync(0xffffffffu, s[j], o);
    }
    const float scale = 0.17677669529663687f;
    float mx = -1e30f;
#pragma unroll
    for(int j=0;j<5;j++){ s[j] *= scale; mx = fmaxf(mx, s[j]); }
    float w[5], sum = 0.f;
#pragma unroll
    for(int j=0;j<5;j++){ w[j] = __expf(s[j]-mx); sum += w[j]; }
    float inv = 1.f / sum;

    float4 vb4 = *(const float4*)(v1b + 4*g);
    float4 v0 = internal ? *(const float4*)(Hv + lb) : vb4;
    float4 v1 = internal ? *(const float4*)(Hv + rb) : vb4;
    float4 v2 = *(const float4*)(Hv + base);
    float4 v3 = *(const float4*)(Ev + base);
    float4 v4 = *(const float4*)(Sv + b*DD + 4*g);

    float ox = (w[0]*v0.x + w[1]*v1.x + w[2]*v2.x + w[3]*v3.x + w[4]*v4.x)*inv;
    float oy = (w[0]*v0.y + w[1]*v1.y + w[2]*v2.y + w[3]*v3.y + w[4]*v4.y)*inv;
    float oz = (w[0]*v0.z + w[1]*v1.z + w[2]*v2.z + w[3]*v3.z + w[4]*v4.z)*inv;
    float ow = (w[0]*v0.w + w[1]*v1.w + w[2]*v2.w + w[3]*v3.w + w[4]*v4.w)*inv;

    __nv_bfloat16 h0,l0,h1,l1;
    __nv_bfloat162 ph, pl;
    split_bf16(ox,h0,l0); split_bf16(oy,h1,l1);
    ph.x=h0; ph.y=h1; pl.x=l0; pl.y=l1;
    *(__nv_bfloat162*)&Ohi[base]   = ph;
    *(__nv_bfloat162*)&Olo[base]   = pl;
    split_bf16(oz,h0,l0); split_bf16(ow,h1,l1);
    ph.x=h0; ph.y=h1; pl.x=l0; pl.y=l1;
    *(__nv_bfloat162*)&Ohi[base+2] = ph;
    *(__nv_bfloat162*)&Olo[base+2] = pl;
}

// ======= step-2 block (runs inside the fused kernel) =========================
__device__ void step2_block(SmemS& ss, int b,
    const float* __restrict__ H, float* __restrict__ state,
    const float* __restrict__ q2w, const float* __restrict__ q2b,
    const float* __restrict__ k2t,
    const float* __restrict__ v2w, const float* __restrict__ v2b,
    const float* __restrict__ o2w, const float* __restrict__ o2b,
    const float* __restrict__ ln2g, const float* __restrict__ ln2b,
    const float* __restrict__ k1w, const float* __restrict__ k1b,
    const float* __restrict__ v1w, const float* __restrict__ v1b,
    float* __restrict__ Sk, float* __restrict__ Sv)
{
    int t = threadIdx.x, warp = t >> 5, lane = t & 31;
    ss.st[t] = state[b*DD + t];
    __syncthreads();
    {
        float a = 0.f;
        for(int k = 0; k < 256; k++) a += ss.st[k] * q2w[(long)k*256 + t];
        ss.q2f[t] = a + q2b[t];
    }
    __syncthreads();
#pragma unroll
    for(int hh = 0; hh < 8; hh++){
        float s = 0.f;
#pragma unroll
        for(int d = 0; d < 32; d++) s += k2t[(long)(hh*32+d)*256 + t] * ss.q2f[hh*32+d];
        ss.qts[hh][t] = s;
    }
    __syncthreads();
    const float scale = 0.17677669529663687f;
    for(int i = warp; i < NN; i += 8){
        const float* hp = H + ((long)b*NN + i)*DD;
        float hv[8];
#pragma unroll
        for(int j=0;j<8;j++) hv[j] = hp[lane + 32*j];
#pragma unroll
        for(int hh=0; hh<8; hh++){
            float s = 0.f;
#pragma unroll
            for(int j=0;j<8;j++) s += hv[j]*ss.qts[hh][lane + 32*j];
#pragma unroll
            for(int o=16;o;o>>=1) s += __shfl_xor_sync(0xffffffffu, s, o);
            if(lane == 0) ss.scs[hh][i] = s * scale;
        }
    }
    __syncthreads();
    {
        float* sp = ss.scs[warp];
        float mx = -1e30f;
        for(int i = lane; i < NN; i += 32) mx = fmaxf(mx, sp[i]);
#pragma unroll
        for(int o=16;o;o>>=1) mx = fmaxf(mx, __shfl_xor_sync(0xffffffffu, mx, o));
        float sum = 0.f;
        for(int i = lane; i < NN; i += 32){ float w = __expf(sp[i]-mx); sp[i] = w; sum += w; }
#pragma unroll
        for(int o=16;o;o>>=1) sum += __shfl_xor_sync(0xffffffffu, sum, o);
        float inv = 1.f/sum;
        for(int i = lane; i < NN; i += 32) sp[i] *= inv;
    }
    __syncthreads();
    {
        float acc[8] = {};
        const float* hp = H + (long)b*NN*DD + t;
        for(int i = 0; i < NN; i++){
            float hval = hp[(long)i*DD];
#pragma unroll
            for(int hh=0; hh<8; hh++) acc[hh] += ss.scs[hh][i]*hval;
        }
#pragma unroll
        for(int hh=0; hh<8; hh++) ss.hb[hh][t] = acc[hh];
    }
    __syncthreads();
    {
        int hh = t >> 5;
        float s = 0.f;
        for(int k = 0; k < 256; k++) s += ss.hb[hh][k] * v2w[(long)k*256 + t];
        ss.o2s[t] = s + v2b[t];
    }
    __syncthreads();
    {
        float s = 0.f;
        for(int k = 0; k < 256; k++) s += ss.o2s[k] * o2w[(long)k*256 + t];
        float u = fmaxf(s + o2b[t], 0.f);
        float v = u;
#pragma unroll
        for(int o=16;o;o>>=1) v += __shfl_xor_sync(0xffffffffu, v, o);
        if(lane==0) ss.wsh[warp] = v;
        __syncthreads();
        if(t < 32){
            float r = (t < 8) ? ss.wsh[t] : 0.f;
#pragma unroll
            for(int o=4;o;o>>=1) r += __shfl_xor_sync(0xffffffffu, r, o);
            if(t==0) ss.stat[0] = r;
        }
        __syncthreads();
        float mean = ss.stat[0] * (1.f/256.f);
        float dx = u - mean;
        v = dx*dx;
#pragma unroll
        for(int o=16;o;o>>=1) v += __shfl_xor_sync(0xffffffffu, v, o);
        if(lane==0) ss.wsh[warp] = v;
        __syncthreads();
        if(t < 32){
            float r = (t < 8) ? ss.wsh[t] : 0.f;
#pragma unroll
            for(int o=4;o;o>>=1) r += __shfl_xor_sync(0xffffffffu, r, o);
            if(t==0) ss.stat[1] = r;
        }
        __syncthreads();
        float sd = sqrtf(ss.stat[1] * (1.f/255.f));
        float y = ln2g[t]*dx/(sd + 1e-6f) + ln2b[t];
        state[b*DD + t] = y;
        ss.ys[t] = y;
    }
    __syncthreads();
    {
        float sk = 0.f, sv = 0.f;
        for(int k = 0; k < 256; k++){
            float yv = ss.ys[k];
            sk += yv * k1w[(long)k*256 + t];
            sv += yv * v1w[(long)k*256 + t];
        }
        Sk[b*DD + t] = sk + k1b[t];
        Sv[b*DD + t] = sv + v1b[t];
    }
}

// ======= fused launch: blocks 0-63 = step2(it), blocks 64+ = qkv(it+1) =======
__global__ __launch_bounds__(256,1) void fused_qkv_step2_kernel(
    const __nv_bfloat16* __restrict__ Ahi, const __nv_bfloat16* __restrict__ Alo,
    const __nv_bfloat16* __restrict__ Whi, const __nv_bfloat16* __restrict__ Wlo,
    const float* q1b, const float* k1b, const float* v1b,
    float* Hq, float* Hk, float* Hv,
    const float* H, float* state,
    const float* q2w, const float* q2b, const float* k2t,
    const float* v2w, const float* v2b, const float* o2w, const float* o2b,
    const float* ln2g, const float* ln2b,
    const float* k1w, const float* v1w,
    float* Sk, float* Sv)
{
    __shared__ SmemU sm;
    if(blockIdx.x < 64){
        step2_block(sm.s, blockIdx.x, H, state, q2w, q2b, k2t, v2w, v2b, o2w, o2b,
                    ln2g, ln2b, k1w, k1b, v1w, v1b, Sk, Sv);
    } else {
        int bx = blockIdx.x - 64;
        int sel = bx / MT;
        int mi  = bx % MT;
        const float* bias = (sel==0) ? q1b : ((sel==1) ? k1b : v1b);
        float*       C    = (sel==0) ? Hq  : ((sel==1) ? Hk  : Hv);
        const __nv_bfloat16* Bh = Whi + (long)sel * (DD*DD);
        const __nv_bfloat16* Bl = Wlo + (long)sel * (DD*DD);
        long bm = (long)mi * 64;
        float c[2][8][4];
        gemm_core(sm.q, Ahi, Alo, Bh, Bl, bm, c);
        gemm_store(c, bias, C, bm);
    }
}

// ------------- final: logits = H @ linw[256,5] + linb ------------------------
__global__ void logits_kernel(const float* __restrict__ H, const float* __restrict__ linw,
                              const float* __restrict__ linb, float* __restrict__ out){
    __shared__ float w[DD*5];
    int t = threadIdx.x;
    for(int i = t; i < DD*5; i += 256) w[i] = linw[i];
    __syncthreads();
    int warp = t >> 5, lane = t & 31;
    long row = (long)blockIdx.x*8 + warp;
    const float* hp = H + row*DD;
    float hr[8];
#pragma unroll
    for(int k=0;k<8;k++) hr[k] = hp[lane + 32*k];
#pragma unroll
    for(int c=0;c<5;c++){
        float a = 0.f;
#pragma unroll
        for(int k=0;k<8;k++) a += hr[k] * w[(lane+32*k)*5 + c];
#pragma unroll
        for(int o=16;o;o>>=1) a += __shfl_xor_sync(0xffffffffu, a, o);
        if(lane==0) out[row*5 + c] = a + linb[c];
    }
}

// ------------------------------- host side -----------------------------------
extern "C" void kernel_launch(void* const* d_in, const int* in_sizes, int n_in,
                              void* d_out, int out_size){
    const int*   wordid = (const int*)  d_in[0];
    const int*   mask   = (const int*)  d_in[1];
    const float* emb    = (const float*)d_in[2];
    const float* q1w=(const float*)d_in[3],  *q1b=(const float*)d_in[4];
    const float* k1w=(const float*)d_in[5],  *k1b=(const float*)d_in[6];
    const float* v1w=(const float*)d_in[7],  *v1b=(const float*)d_in[8];
    const float* o1w=(const float*)d_in[9],  *o1b=(const float*)d_in[10];
    const float* q2w=(const float*)d_in[11], *q2b=(const float*)d_in[12];
    const float* k2w=(const float*)d_in[13], *k2b=(const float*)d_in[14];
    const float* v2w=(const float*)d_in[15], *v2b=(const float*)d_in[16];
    const float* o2w=(const float*)d_in[17], *o2b=(const float*)d_in[18];
    const float* ln1g=(const float*)d_in[19],*ln1bb=(const float*)d_in[20];
    const float* ln2g=(const float*)d_in[21],*ln2bb=(const float*)d_in[22];
    const float* linw=(const float*)d_in[23],*linb=(const float*)d_in[24];
    float* out = (float*)d_out;
    (void)k2b;  // uniform score shift -> softmax invariant

    float *H,*Ek,*Ev,*Hq,*Hk,*Hv,*state,*Sk,*Sv,*k2t;
    __nv_bfloat16 *Hhi,*Hlo,*Ohi,*Olo,*Whi,*Wlo;
    cudaGetSymbolAddress((void**)&H,  g_H);
    cudaGetSymbolAddress((void**)&Ek, g_Ek);
    cudaGetSymbolAddress((void**)&Ev, g_Ev);
    cudaGetSymbolAddress((void**)&Hq, g_Hq);
    cudaGetSymbolAddress((void**)&Hk, g_Hk);
    cudaGetSymbolAddress((void**)&Hv, g_Hv);
    cudaGetSymbolAddress((void**)&state, g_state);
    cudaGetSymbolAddress((void**)&Sk, g_Sk);
    cudaGetSymbolAddress((void**)&Sv, g_Sv);
    cudaGetSymbolAddress((void**)&k2t, g_k2t);
    cudaGetSymbolAddress((void**)&Hhi, g_Hhi);
    cudaGetSymbolAddress((void**)&Hlo, g_Hlo);
    cudaGetSymbolAddress((void**)&Ohi, g_Ohi);
    cudaGetSymbolAddress((void**)&Olo, g_Olo);
    cudaGetSymbolAddress((void**)&Whi, g_Whi);
    cudaGetSymbolAddress((void**)&Wlo, g_Wlo);

    wsplit_kernel<<<dim3(DD*DD/256, 4), 256>>>(q1w, k1w, v1w, o1w, Whi, Wlo);
    trans_kernel <<<dim3(8,8), 256>>>(k2w, k2t);
    embed_kernel    <<<MR, 256>>>(wordid, mask, emb, H, Hhi, Hlo);
    initstate_kernel<<<BB, 256>>>(H, state);
    sgemm_kernel<<<dim3(4,2), 256>>>(state, k1w, k1b, Sk, v1w, v1b, Sv);

    // qkv for iteration 0 (h == e, so k1/v1 outputs double as loop-invariant Ek/Ev)
    tcgemm3_kernel<<<dim3(MT,3), 256>>>(Hhi, Hlo, Whi, Wlo,
                                        q1b, k1b, v1b, Hq, Ek, Ev);

    for(int it = 0; it < 5; it++){
        const float* kBuf = (it == 0) ? Ek : Hk;
        const float* vBuf = (it == 0) ? Ev : Hv;
        attn1_kernel<<<MR/4, 256>>>(Hq, kBuf, vBuf, Ek, Ev, Sk, Sv, k1b, v1b, Ohi, Olo);
        tcgemm_ln_kernel<<<MT, 256>>>(Ohi, Olo, Whi + 3L*DD*DD, Wlo + 3L*DD*DD,
                                      o1b, ln1g, ln1bb, H, Hhi, Hlo);
        if(it < 4){
            // step2(it) runs concurrently with qkv(it+1) in one launch;
            // step2 at it==4 would compute a state that is never read -> skipped.
            fused_qkv_step2_kernel<<<64 + 3*MT, 256>>>(
                Hhi, Hlo, Whi, Wlo, q1b, k1b, v1b, Hq, Hk, Hv,
                H, state, q2w, q2b, k2t, v2w, v2b, o2w, o2b,
                ln2g, ln2bb, k1w, v1w, Sk, Sv);
        }
    }

    logits_kernel<<<MR/8, 256>>>(H, linw, linb, out);
}

// round 12
// speedup vs baseline: 1.5650x; 1.0381x over previous
#include <cuda_runtime.h>
#include <cuda_bf16.h>
#include <stdint.h>

// Problem constants
#define BB 64
#define NN 511
#define DD 256
#define MR (BB*NN)   // 32704 rows
#define MT (MR/64)   // 511 M tiles

// ---------------- scratch (device globals; no allocation allowed) -------------
__device__ float g_H [MR*DD];
__device__ float g_Ek[MR*DD];
__device__ float g_Ev[MR*DD];
__device__ float g_Hq[MR*DD];
__device__ float g_Hk[MR*DD];
__device__ float g_Hv[MR*DD];
__device__ float g_state[BB*DD];
__device__ float g_Sk[BB*DD];
__device__ float g_Sv[BB*DD];
__device__ float g_k2t[DD*DD];      // k2w transposed
__device__ float g_ispart[4*BB*DD]; // initstate partials
// bf16 split operands for tensor-core GEMMs
__device__ __nv_bfloat16 g_Hhi[MR*DD];
__device__ __nv_bfloat16 g_Hlo[MR*DD];
__device__ __nv_bfloat16 g_Ohi[MR*DD];
__device__ __nv_bfloat16 g_Olo[MR*DD];
__device__ __nv_bfloat16 g_Whi[4*DD*DD];   // [q1,k1,v1,o1]
__device__ __nv_bfloat16 g_Wlo[4*DD*DD];

__device__ __forceinline__ void split_bf16(float x, __nv_bfloat16& h, __nv_bfloat16& l){
    h = __float2bfloat16_rn(x);
    l = __float2bfloat16_rn(x - __bfloat162float(h));
}

// ---------------- weight split (4 weights in one launch) ---------------------
__global__ void wsplit_kernel(const float* W0, const float* W1, const float* W2,
                              const float* W3,
                              __nv_bfloat16* __restrict__ hi, __nv_bfloat16* __restrict__ lo){
    int w = blockIdx.y;
    const float* W = (w==0)?W0:((w==1)?W1:((w==2)?W2:W3));
    int i = blockIdx.x*256 + threadIdx.x;
    long o = (long)w*DD*DD + i;
    split_bf16(W[i], hi[o], lo[o]);
}

// ---------------- fp32 transpose (k2w) ---------------------------------------
__global__ void trans_kernel(const float* __restrict__ W, float* __restrict__ Wt){
    __shared__ float t[32][33];
    int bx = blockIdx.x*32, by = blockIdx.y*32;
    int x = threadIdx.x & 31, y0 = threadIdx.x >> 5;
#pragma unroll
    for(int i=0;i<4;i++){ int y=y0*4+i; t[y][x] = W[(by+y)*256 + bx + x]; }
    __syncthreads();
#pragma unroll
    for(int i=0;i<4;i++){ int y=y0*4+i; Wt[(long)(bx+y)*256 + by + x] = t[x][y]; }
}

// ---------------- embedding ---------------------------------------------------
__global__ void embed_kernel(const int* __restrict__ wordid, const int* __restrict__ mask,
                             const float* __restrict__ emb, float* __restrict__ H,
                             __nv_bfloat16* __restrict__ Hhi, __nv_bfloat16* __restrict__ Hlo){
    long node = blockIdx.x;
    int  t    = threadIdx.x;
    int wid = wordid[node];
    int m   = mask[node];
    float v = emb[(long)(wid*m)*DD + t] * (float)m;
    H[node*DD + t] = v;
    split_bf16(v, Hhi[node*DD + t], Hlo[node*DD + t]);
}

// ---------------- state init (partials + deterministic combine) ---------------
__global__ void initstate_part(const float* __restrict__ H, float* __restrict__ part){
    int pb = blockIdx.y, b = blockIdx.x, t = threadIdx.x;
    int i0 = pb*128;
    int i1 = (i0 + 128 < NN) ? i0 + 128 : NN;
    const float* p = H + ((long)b*NN + i0)*DD + t;
    float s = 0.f;
    for(int i = i0; i < i1; i++, p += DD) s += *p;
    part[(pb*BB + b)*DD + t] = s;
}
__global__ void initstate_comb(const float* __restrict__ part, float* __restrict__ state){
    int b = blockIdx.x, t = threadIdx.x;
    float s = part[(0*BB+b)*DD+t] + part[(1*BB+b)*DD+t]
            + part[(2*BB+b)*DD+t] + part[(3*BB+b)*DD+t];
    state[b*DD + t] = s * (1.f/(float)NN);
}

// ---------------- tensor-core bf16x3 GEMM core (cp.async 2-stage) -------------
__device__ __forceinline__ void ldsm4(uint32_t* r, const void* p){
    uint32_t a = (uint32_t)__cvta_generic_to_shared(p);
    asm volatile("ldmatrix.sync.aligned.m8n8.x4.shared.b16 {%0,%1,%2,%3}, [%4];"
        : "=r"(r[0]),"=r"(r[1]),"=r"(r[2]),"=r"(r[3]) : "r"(a));
}
__device__ __forceinline__ void ldsm4t(uint32_t* r, const void* p){
    uint32_t a = (uint32_t)__cvta_generic_to_shared(p);
    asm volatile("ldmatrix.sync.aligned.m8n8.x4.trans.shared.b16 {%0,%1,%2,%3}, [%4];"
        : "=r"(r[0]),"=r"(r[1]),"=r"(r[2]),"=r"(r[3]) : "r"(a));
}
__device__ __forceinline__ void mma16816(float* c, const uint32_t* a, const uint32_t* b){
    asm volatile("mma.sync.aligned.m16n8k16.row.col.f32.bf16.bf16.f32 "
        "{%0,%1,%2,%3}, {%4,%5,%6,%7}, {%8,%9}, {%0,%1,%2,%3};"
        : "+f"(c[0]),"+f"(c[1]),"+f"(c[2]),"+f"(c[3])
        : "r"(a[0]),"r"(a[1]),"r"(a[2]),"r"(a[3]), "r"(b[0]),"r"(b[1]));
}
__device__ __forceinline__ void cpa16(void* dst, const void* src){
    uint32_t d = (uint32_t)__cvta_generic_to_shared(dst);
    asm volatile("cp.async.cg.shared.global [%0], [%1], 16;\n" :: "r"(d), "l"(src));
}
__device__ __forceinline__ void cpa_commit(){ asm volatile("cp.async.commit_group;\n"); }
template<int N> __device__ __forceinline__ void cpa_wait(){ asm volatile("cp.async.wait_group %0;\n" :: "n"(N)); }

struct SmemQ2 {
    __nv_bfloat16 As[2][2][64][40];   // [stage][hi/lo][m][k]
    __nv_bfloat16 Bs[2][2][32][264];  // [stage][hi/lo][k][n]
};
struct SmemS {
    float st[256], q2f[256], qts[8][256], scs[8][NN], hb[8][256];
    float o2s[256], ys[256], wsh[8], stat[2];
};
union SmemU2 { SmemQ2 q; SmemS s; };
#define GEMM_SMEM ((int)sizeof(SmemU2))

__device__ __forceinline__ void gemm_load_stage(SmemQ2& sq, int st, int kt, long bm,
    const __nv_bfloat16* __restrict__ Ahi, const __nv_bfloat16* __restrict__ Alo,
    const __nv_bfloat16* __restrict__ Bh,  const __nv_bfloat16* __restrict__ Bl)
{
    int tid = threadIdx.x, lane = tid & 31, warp = tid >> 5;
    int am = tid >> 2, aseg = (tid & 3) * 8;
    long asrc = (bm + am)*256 + kt*32 + aseg;
    cpa16(&sq.As[st][0][am][aseg], Ahi + asrc);
    cpa16(&sq.As[st][1][am][aseg], Alo + asrc);
    int bn = lane * 8;
#pragma unroll
    for(int j = 0; j < 4; j++){
        long bsrc = ((long)(kt*32 + warp + 8*j))*256 + bn;
        cpa16(&sq.Bs[st][0][warp + 8*j][bn], Bh + bsrc);
        cpa16(&sq.Bs[st][1][warp + 8*j][bn], Bl + bsrc);
    }
    cpa_commit();
}

__device__ __forceinline__ void gemm_core(SmemQ2& sq,
    const __nv_bfloat16* __restrict__ Ahi, const __nv_bfloat16* __restrict__ Alo,
    const __nv_bfloat16* __restrict__ Bh, const __nv_bfloat16* __restrict__ Bl,
    long bm, float c[2][8][4])
{
    int tid = threadIdx.x, lane = tid & 31, warp = tid >> 5;
    int wm = warp >> 2, wn = warp & 3;
#pragma unroll
    for(int i=0;i<2;i++)
#pragma unroll
        for(int j=0;j<8;j++)
#pragma unroll
            for(int k=0;k<4;k++) c[i][j][k]=0.f;

    gemm_load_stage(sq, 0, 0, bm, Ahi, Alo, Bh, Bl);
    gemm_load_stage(sq, 1, 1, bm, Ahi, Alo, Bh, Bl);

    int q = lane >> 3, r = lane & 7;
    int arow = wm*32 + (q&1)*8 + r;
    int acol = (q>>1)*8;
    int bkrow = (q&1)*8 + r;
    int bcol = wn*64 + (q>>1)*8;

    for(int kt = 0; kt < 8; kt++){
        if(kt < 7){ cpa_wait<1>(); } else { cpa_wait<0>(); }
        __syncthreads();
        int st = kt & 1;
#pragma unroll
        for(int k16 = 0; k16 < 2; k16++){
            uint32_t ah[2][4], al[2][4];
#pragma unroll
            for(int mt=0; mt<2; mt++){
                ldsm4(ah[mt], &sq.As[st][0][arow + mt*16][acol + k16*16]);
                ldsm4(al[mt], &sq.As[st][1][arow + mt*16][acol + k16*16]);
            }
            uint32_t bh[8][2], bl[8][2];
#pragma unroll
            for(int p=0; p<4; p++){
                uint32_t t4[4];
                ldsm4t(t4, &sq.Bs[st][0][bkrow + k16*16][bcol + p*16]);
                bh[2*p][0]=t4[0]; bh[2*p][1]=t4[1]; bh[2*p+1][0]=t4[2]; bh[2*p+1][1]=t4[3];
                ldsm4t(t4, &sq.Bs[st][1][bkrow + k16*16][bcol + p*16]);
                bl[2*p][0]=t4[0]; bl[2*p][1]=t4[1]; bl[2*p+1][0]=t4[2]; bl[2*p+1][1]=t4[3];
            }
#pragma unroll
            for(int mt=0; mt<2; mt++)
#pragma unroll
                for(int nt=0; nt<8; nt++){
                    mma16816(c[mt][nt], ah[mt], bh[nt]);
                    mma16816(c[mt][nt], ah[mt], bl[nt]);
                    mma16816(c[mt][nt], al[mt], bh[nt]);
                }
        }
        __syncthreads();
        if(kt < 6){ gemm_load_stage(sq, st, kt+2, bm, Ahi, Alo, Bh, Bl); }
    }
}

// ---------- plain GEMM epilogue -----------------------------------------------
__device__ __forceinline__ void gemm_store(float c[2][8][4], const float* bias,
                                           float* C, long bm){
    int tid = threadIdx.x, lane = tid & 31, warp = tid >> 5;
    int wm = warp >> 2, wn = warp & 3;
    int crow = wm*32 + (lane>>2);
    int ccol = wn*64 + (lane&3)*2;
#pragma unroll
    for(int mt=0; mt<2; mt++)
#pragma unroll
        for(int nt=0; nt<8; nt++){
            long row = bm + crow + mt*16;
            int col = ccol + nt*8;
            float b0v = bias[col], b1v = bias[col+1];
            float2 v0; v0.x = c[mt][nt][0] + b0v; v0.y = c[mt][nt][1] + b1v;
            *(float2*)&C[row*256 + col] = v0;
            float2 v1; v1.x = c[mt][nt][2] + b0v; v1.y = c[mt][nt][3] + b1v;
            *(float2*)&C[(row+8)*256 + col] = v1;
        }
}

// ---------- standalone 3-output GEMM (prologue qkv_0) -------------------------
__global__ __launch_bounds__(256,2) void tcgemm3_kernel(
    const __nv_bfloat16* __restrict__ Ahi, const __nv_bfloat16* __restrict__ Alo,
    const __nv_bfloat16* __restrict__ Whi, const __nv_bfloat16* __restrict__ Wlo,
    const float* bias0, const float* bias1, const float* bias2,
    float* C0, float* C1, float* C2)
{
    extern __shared__ char smraw[];
    SmemQ2& sq = reinterpret_cast<SmemU2*>(smraw)->q;
    int sel = blockIdx.y;
    const float* bias = (sel==0) ? bias0 : ((sel==1) ? bias1 : bias2);
    float*       C    = (sel==0) ? C0    : ((sel==1) ? C1    : C2);
    const __nv_bfloat16* Bh = Whi + (long)sel * (DD*DD);
    const __nv_bfloat16* Bl = Wlo + (long)sel * (DD*DD);
    long bm = (long)blockIdx.x * 64;
    float c[2][8][4];
    gemm_core(sq, Ahi, Alo, Bh, Bl, bm, c);
    gemm_store(c, bias, C, bm);
}

// ---------- GEMM + bias + relu + LayerNorm epilogue (o1 projection) -----------
__global__ __launch_bounds__(256,2) void tcgemm_ln_kernel(
    const __nv_bfloat16* __restrict__ Ahi, const __nv_bfloat16* __restrict__ Alo,
    const __nv_bfloat16* __restrict__ Bh, const __nv_bfloat16* __restrict__ Bl,
    const float* __restrict__ bias, const float* __restrict__ gam,
    const float* __restrict__ bet,
    float* __restrict__ Y, __nv_bfloat16* __restrict__ Yhi, __nv_bfloat16* __restrict__ Ylo)
{
    extern __shared__ char smraw[];
    SmemQ2& sq = reinterpret_cast<SmemU2*>(smraw)->q;
    __shared__ float red1[4][64];
    __shared__ float rowm[64];
    __shared__ float rowi[64];
    __shared__ float gsh[256], bsh[256], bbsh[256];
    gsh[threadIdx.x]  = gam[threadIdx.x];
    bsh[threadIdx.x]  = bet[threadIdx.x];
    bbsh[threadIdx.x] = bias[threadIdx.x];
    long bm = (long)blockIdx.x * 64;
    float c[2][8][4];
    gemm_core(sq, Ahi, Alo, Bh, Bl, bm, c);

    int tid = threadIdx.x, lane = tid & 31, warp = tid >> 5;
    int wm = warp >> 2, wn = warp & 3;
    int crow0 = wm*32 + (lane>>2);
    int ccol = wn*64 + (lane&3)*2;
#pragma unroll
    for(int mt=0; mt<2; mt++)
#pragma unroll
        for(int nt=0; nt<8; nt++){
            int col = ccol + nt*8;
            c[mt][nt][0] = fmaxf(c[mt][nt][0] + bbsh[col],   0.f);
            c[mt][nt][1] = fmaxf(c[mt][nt][1] + bbsh[col+1], 0.f);
            c[mt][nt][2] = fmaxf(c[mt][nt][2] + bbsh[col],   0.f);
            c[mt][nt][3] = fmaxf(c[mt][nt][3] + bbsh[col+1], 0.f);
        }
#pragma unroll
    for(int mt=0; mt<2; mt++){
        float sA = 0.f, sB = 0.f;
#pragma unroll
        for(int nt=0; nt<8; nt++){
            sA += c[mt][nt][0] + c[mt][nt][1];
            sB += c[mt][nt][2] + c[mt][nt][3];
        }
        sA += __shfl_xor_sync(0xffffffffu, sA, 1); sA += __shfl_xor_sync(0xffffffffu, sA, 2);
        sB += __shfl_xor_sync(0xffffffffu, sB, 1); sB += __shfl_xor_sync(0xffffffffu, sB, 2);
        if((lane&3) == 0){
            int rl = crow0 + mt*16;
            red1[wn][rl]   = sA;
            red1[wn][rl+8] = sB;
        }
    }
    __syncthreads();
    if(tid < 64) rowm[tid] = (red1[0][tid]+red1[1][tid]+red1[2][tid]+red1[3][tid]) * (1.f/256.f);
    __syncthreads();
#pragma unroll
    for(int mt=0; mt<2; mt++){
        int rl = crow0 + mt*16;
        float m0 = rowm[rl], m1 = rowm[rl+8];
        float sA = 0.f, sB = 0.f;
#pragma unroll
        for(int nt=0; nt<8; nt++){
            float d0 = c[mt][nt][0]-m0, d1 = c[mt][nt][1]-m0;
            float d2 = c[mt][nt][2]-m1, d3 = c[mt][nt][3]-m1;
            sA += d0*d0 + d1*d1;
            sB += d2*d2 + d3*d3;
        }
        sA += __shfl_xor_sync(0xffffffffu, sA, 1); sA += __shfl_xor_sync(0xffffffffu, sA, 2);
        sB += __shfl_xor_sync(0xffffffffu, sB, 1); sB += __shfl_xor_sync(0xffffffffu, sB, 2);
        if((lane&3) == 0){
            red1[wn][rl]   = sA;
            red1[wn][rl+8] = sB;
        }
    }
    __syncthreads();
    if(tid < 64){
        float var = (red1[0][tid]+red1[1][tid]+red1[2][tid]+red1[3][tid]) * (1.f/255.f);
        rowi[tid] = 1.f / (sqrtf(var) + 1e-6f);
    }
    __syncthreads();
#pragma unroll
    for(int mt=0; mt<2; mt++){
        int rl = crow0 + mt*16;
        float m0 = rowm[rl], i0 = rowi[rl];
        float m1 = rowm[rl+8], i1 = rowi[rl+8];
        long row0 = bm + rl, row1 = row0 + 8;
#pragma unroll
        for(int nt=0; nt<8; nt++){
            int col = ccol + nt*8;
            float g0 = gsh[col], g1 = gsh[col+1], be0 = bsh[col], be1 = bsh[col+1];
            float y0 = g0*(c[mt][nt][0]-m0)*i0 + be0;
            float y1 = g1*(c[mt][nt][1]-m0)*i0 + be1;
            float y2 = g0*(c[mt][nt][2]-m1)*i1 + be0;
            float y3 = g1*(c[mt][nt][3]-m1)*i1 + be1;
            float2 f0; f0.x=y0; f0.y=y1;
            *(float2*)&Y[row0*256 + col] = f0;
            float2 f1; f1.x=y2; f1.y=y3;
            *(float2*)&Y[row1*256 + col] = f1;
            __nv_bfloat16 h0,l0,h1,l1;
            split_bf16(y0,h0,l0); split_bf16(y1,h1,l1);
            __nv_bfloat162 ph; ph.x=h0; ph.y=h1;
            __nv_bfloat162 pl; pl.x=l0; pl.y=l1;
            *(__nv_bfloat162*)&Yhi[row0*256 + col] = ph;
            *(__nv_bfloat162*)&Ylo[row0*256 + col] = pl;
            split_bf16(y2,h0,l0); split_bf16(y3,h1,l1);
            ph.x=h0; ph.y=h1; pl.x=l0; pl.y=l1;
            *(__nv_bfloat162*)&Yhi[row1*256 + col] = ph;
            *(__nv_bfloat162*)&Ylo[row1*256 + col] = pl;
        }
    }
}

// ------- fp32 SGEMM for the tiny 64-row state GEMMs (prologue Sk/Sv) ---------
__global__ void sgemm_kernel(const float* __restrict__ A, const float* __restrict__ W0,
                             const float* __restrict__ b0v, float* __restrict__ C0v,
                             const float* __restrict__ W1, const float* __restrict__ b1v,
                             float* __restrict__ C1v){
    __shared__ float As[16][68];
    __shared__ float Bs[16][64];
    int tid = threadIdx.x;
    const float* W    = blockIdx.y ? W1  : W0;
    const float* bias = blockIdx.y ? b1v : b0v;
    float*       C    = blockIdx.y ? C1v : C0v;
    int  bn = blockIdx.x * 64;
    int ar = tid >> 2,  ac = (tid & 3)  * 4;
    int br = tid >> 4,  bc = (tid & 15) * 4;
    int tx = tid & 15,  ty = tid >> 4;
    float acc[4][4] = {};
    const float* Ap = A + ar*256 + ac;
    const float* Wp = W + (long)br*256 + bn + bc;
    for(int k0 = 0; k0 < 256; k0 += 16){
        float4 av = *(const float4*)(Ap + k0);
        As[ac+0][ar] = av.x; As[ac+1][ar] = av.y;
        As[ac+2][ar] = av.z; As[ac+3][ar] = av.w;
        *(float4*)&Bs[br][bc] = *(const float4*)(Wp + (long)k0*256);
        __syncthreads();
#pragma unroll
        for(int kk = 0; kk < 16; kk++){
            float a[4], b[4];
#pragma unroll
            for(int i=0;i<4;i++) a[i] = As[kk][ty*4+i];
#pragma unroll
            for(int j=0;j<4;j++) b[j] = Bs[kk][tx*4+j];
#pragma unroll
            for(int i=0;i<4;i++)
#pragma unroll
                for(int j=0;j<4;j++) acc[i][j] += a[i]*b[j];
        }
        __syncthreads();
    }
#pragma unroll
    for(int i=0;i<4;i++){
        long row = ty*4 + i;
        float4 o;
        o.x = acc[i][0] + bias[bn + tx*4 + 0];
        o.y = acc[i][1] + bias[bn + tx*4 + 1];
        o.z = acc[i][2] + bias[bn + tx*4 + 2];
        o.w = acc[i][3] + bias[bn + tx*4 + 3];
        *(float4*)(C + row*256 + bn + tx*4) = o;
    }
}

// ------------- step-1 attention, float4 / 64-threads-per-node ----------------
__global__ void attn1_kernel(const float* __restrict__ Hq, const float* __restrict__ Hk,
                             const float* __restrict__ Hv,
                             const float* __restrict__ Ek, const float* __restrict__ Ev,
                             const float* __restrict__ Sk, const float* __restrict__ Sv,
                             const float* __restrict__ k1b, const float* __restrict__ v1b,
                             __nv_bfloat16* __restrict__ Ohi, __nv_bfloat16* __restrict__ Olo){
    int tid = threadIdx.x;
    int nb  = blockIdx.x*4 + (tid>>6);   // 4 nodes per block
    int g   = tid & 63;                  // 64 threads per node, float4 each
    int node = nb % NN;
    int b    = nb / NN;
    long base = (long)nb*DD + 4*g;
    bool internal = node < 255;
    long lb = internal ? ((long)(nb + node + 1)*DD + 4*g) : base;
    long rb = internal ? (lb + DD) : base;

    float4 qv  = *(const float4*)(Hq + base);
    float4 kb4 = *(const float4*)(k1b + 4*g);
    float4 k0 = internal ? *(const float4*)(Hk + lb) : kb4;
    float4 k1 = internal ? *(const float4*)(Hk + rb) : kb4;
    float4 k2 = *(const float4*)(Hk + base);
    float4 k3 = *(const float4*)(Ek + base);
    float4 k4 = *(const float4*)(Sk + b*DD + 4*g);

    float s[5];
    s[0] = qv.x*k0.x + qv.y*k0.y + qv.z*k0.z + qv.w*k0.w;
    s[1] = qv.x*k1.x + qv.y*k1.y + qv.z*k1.z + qv.w*k1.w;
    s[2] = qv.x*k2.x + qv.y*k2.y + qv.z*k2.z + qv.w*k2.w;
    s[3] = qv.x*k3.x + qv.y*k3.y + qv.z*k3.z + qv.w*k3.w;
    s[4] = qv.x*k4.x + qv.y*k4.y + qv.z*k4.z + qv.w*k4.w;
#pragma unroll
    for(int o = 4; o; o >>= 1){
#pragma unroll
        for(int j=0;j<5;j++) s[j] += __shfl_xor_sync(0xffffffffu, s[j], o);
    }
    const float scale = 0.17677669529663687f;
    float mx = -1e30f;
#pragma unroll
    for(int j=0;j<5;j++){ s[j] *= scale; mx = fmaxf(mx, s[j]); }
    float w[5], sum = 0.f;
#pragma unroll
    for(int j=0;j<5;j++){ w[j] = __expf(s[j]-mx); sum += w[j]; }
    float inv = 1.f / sum;

    float4 vb4 = *(const float4*)(v1b + 4*g);
    float4 v0 = internal ? *(const float4*)(Hv + lb) : vb4;
    float4 v1 = internal ? *(const float4*)(Hv + rb) : vb4;
    float4 v2 = *(const float4*)(Hv + base);
    float4 v3 = *(const float4*)(Ev + base);
    float4 v4 = *(const float4*)(Sv + b*DD + 4*g);

    float ox = (w[0]*v0.x + w[1]*v1.x + w[2]*v2.x + w[3]*v3.x + w[4]*v4.x)*inv;
    float oy = (w[0]*v0.y + w[1]*v1.y + w[2]*v2.y + w[3]*v3.y + w[4]*v4.y)*inv;
    float oz = (w[0]*v0.z + w[1]*v1.z + w[2]*v2.z + w[3]*v3.z + w[4]*v4.z)*inv;
    float ow = (w[0]*v0.w + w[1]*v1.w + w[2]*v2.w + w[3]*v3.w + w[4]*v4.w)*inv;

    __nv_bfloat16 h0,l0,h1,l1;
    __nv_bfloat162 ph, pl;
    split_bf16(ox,h0,l0); split_bf16(oy,h1,l1);
    ph.x=h0; ph.y=h1; pl.x=l0; pl.y=l1;
    *(__nv_bfloat162*)&Ohi[base]   = ph;
    *(__nv_bfloat162*)&Olo[base]   = pl;
    split_bf16(oz,h0,l0); split_bf16(ow,h1,l1);
    ph.x=h0; ph.y=h1; pl.x=l0; pl.y=l1;
    *(__nv_bfloat162*)&Ohi[base+2] = ph;
    *(__nv_bfloat162*)&Olo[base+2] = pl;
}

// ======= step-2 block (runs inside the fused kernel) =========================
__device__ void step2_block(SmemS& ss, int b,
    const float* __restrict__ H, float* __restrict__ state,
    const float* __restrict__ q2w, const float* __restrict__ q2b,
    const float* __restrict__ k2t,
    const float* __restrict__ v2w, const float* __restrict__ v2b,
    const float* __restrict__ o2w, const float* __restrict__ o2b,
    const float* __restrict__ ln2g, const float* __restrict__ ln2b,
    const float* __restrict__ k1w, const float* __restrict__ k1b,
    const float* __restrict__ v1w, const float* __restrict__ v1b,
    float* __restrict__ Sk, float* __restrict__ Sv)
{
    int t = threadIdx.x, warp = t >> 5, lane = t & 31;
    ss.st[t] = state[b*DD + t];
    __syncthreads();
    {
        float a = 0.f;
        for(int k = 0; k < 256; k++) a += ss.st[k] * q2w[(long)k*256 + t];
        ss.q2f[t] = a + q2b[t];
    }
    __syncthreads();
#pragma unroll
    for(int hh = 0; hh < 8; hh++){
        float s = 0.f;
#pragma unroll
        for(int d = 0; d < 32; d++) s += k2t[(long)(hh*32+d)*256 + t] * ss.q2f[hh*32+d];
        ss.qts[hh][t] = s;
    }
    __syncthreads();
    const float scale = 0.17677669529663687f;
    for(int i = warp; i < NN; i += 8){
        const float* hp = H + ((long)b*NN + i)*DD;
        float hv[8];
#pragma unroll
        for(int j=0;j<8;j++) hv[j] = hp[lane + 32*j];
#pragma unroll
        for(int hh=0; hh<8; hh++){
            float s = 0.f;
#pragma unroll
            for(int j=0;j<8;j++) s += hv[j]*ss.qts[hh][lane + 32*j];
#pragma unroll
            for(int o=16;o;o>>=1) s += __shfl_xor_sync(0xffffffffu, s, o);
            if(lane == 0) ss.scs[hh][i] = s * scale;
        }
    }
    __syncthreads();
    {
        float* sp = ss.scs[warp];
        float mx = -1e30f;
        for(int i = lane; i < NN; i += 32) mx = fmaxf(mx, sp[i]);
#pragma unroll
        for(int o=16;o;o>>=1) mx = fmaxf(mx, __shfl_xor_sync(0xffffffffu, mx, o));
        float sum = 0.f;
        for(int i = lane; i < NN; i += 32){ float w = __expf(sp[i]-mx); sp[i] = w; sum += w; }
#pragma unroll
        for(int o=16;o;o>>=1) sum += __shfl_xor_sync(0xffffffffu, sum, o);
        float inv = 1.f/sum;
        for(int i = lane; i < NN; i += 32) sp[i] *= inv;
    }
    __syncthreads();
    {
        float acc[8] = {};
        const float* hp = H + (long)b*NN*DD + t;
        for(int i = 0; i < NN; i++){
            float hval = hp[(long)i*DD];
#pragma unroll
            for(int hh=0; hh<8; hh++) acc[hh] += ss.scs[hh][i]*hval;
        }
#pragma unroll
        for(int hh=0; hh<8; hh++) ss.hb[hh][t] = acc[hh];
    }
    __syncthreads();
    {
        int hh = t >> 5;
        float s = 0.f;
        for(int k = 0; k < 256; k++) s += ss.hb[hh][k] * v2w[(long)k*256 + t];
        ss.o2s[t] = s + v2b[t];
    }
    __syncthreads();
    {
        float s = 0.f;
        for(int k = 0; k < 256; k++) s += ss.o2s[k] * o2w[(long)k*256 + t];
        float u = fmaxf(s + o2b[t], 0.f);
        float v = u;
#pragma unroll
        for(int o=16;o;o>>=1) v += __shfl_xor_sync(0xffffffffu, v, o);
        if(lane==0) ss.wsh[warp] = v;
        __syncthreads();
        if(t < 32){
            float r = (t < 8) ? ss.wsh[t] : 0.f;
#pragma unroll
            for(int o=4;o;o>>=1) r += __shfl_xor_sync(0xffffffffu, r, o);
            if(t==0) ss.stat[0] = r;
        }
        __syncthreads();
        float mean = ss.stat[0] * (1.f/256.f);
        float dx = u - mean;
        v = dx*dx;
#pragma unroll
        for(int o=16;o;o>>=1) v += __shfl_xor_sync(0xffffffffu, v, o);
        if(lane==0) ss.wsh[warp] = v;
        __syncthreads();
        if(t < 32){
            float r = (t < 8) ? ss.wsh[t] : 0.f;
#pragma unroll
            for(int o=4;o;o>>=1) r += __shfl_xor_sync(0xffffffffu, r, o);
            if(t==0) ss.stat[1] = r;
        }
        __syncthreads();
        float sd = sqrtf(ss.stat[1] * (1.f/255.f));
        float y = ln2g[t]*dx/(sd + 1e-6f) + ln2b[t];
        state[b*DD + t] = y;
        ss.ys[t] = y;
    }
    __syncthreads();
    {
        float sk = 0.f, sv = 0.f;
        for(int k = 0; k < 256; k++){
            float yv = ss.ys[k];
            sk += yv * k1w[(long)k*256 + t];
            sv += yv * v1w[(long)k*256 + t];
        }
        Sk[b*DD + t] = sk + k1b[t];
        Sv[b*DD + t] = sv + v1b[t];
    }
}

// ======= fused launch: blocks 0-63 = step2(it), blocks 64+ = qkv(it+1) =======
__global__ __launch_bounds__(256,2) void fused_qkv_step2_kernel(
    const __nv_bfloat16* __restrict__ Ahi, const __nv_bfloat16* __restrict__ Alo,
    const __nv_bfloat16* __restrict__ Whi, const __nv_bfloat16* __restrict__ Wlo,
    const float* q1b, const float* k1b, const float* v1b,
    float* Hq, float* Hk, float* Hv,
    const float* H, float* state,
    const float* q2w, const float* q2b, const float* k2t,
    const float* v2w, const float* v2b, const float* o2w, const float* o2b,
    const float* ln2g, const float* ln2b,
    const float* k1w, const float* v1w,
    float* Sk, float* Sv)
{
    extern __shared__ char smraw[];
    SmemU2& sm = *reinterpret_cast<SmemU2*>(smraw);
    if(blockIdx.x < 64){
        step2_block(sm.s, blockIdx.x, H, state, q2w, q2b, k2t, v2w, v2b, o2w, o2b,
                    ln2g, ln2b, k1w, k1b, v1w, v1b, Sk, Sv);
    } else {
        int bx = blockIdx.x - 64;
        int sel = bx / MT;
        int mi  = bx % MT;
        const float* bias = (sel==0) ? q1b : ((sel==1) ? k1b : v1b);
        float*       C    = (sel==0) ? Hq  : ((sel==1) ? Hk  : Hv);
        const __nv_bfloat16* Bh = Whi + (long)sel * (DD*DD);
        const __nv_bfloat16* Bl = Wlo + (long)sel * (DD*DD);
        long bm = (long)mi * 64;
        float c[2][8][4];
        gemm_core(sm.q, Ahi, Alo, Bh, Bl, bm, c);
        gemm_store(c, bias, C, bm);
    }
}

// ------------- final: logits = H @ linw[256,5] + linb ------------------------
__global__ void logits_kernel(const float* __restrict__ H, const float* __restrict__ linw,
                              const float* __restrict__ linb, float* __restrict__ out){
    __shared__ float w[DD*5];
    int t = threadIdx.x;
    for(int i = t; i < DD*5; i += 256) w[i] = linw[i];
    __syncthreads();
    int warp = t >> 5, lane = t & 31;
    long row = (long)blockIdx.x*8 + warp;
    const float* hp = H + row*DD;
    float hr[8];
#pragma unroll
    for(int k=0;k<8;k++) hr[k] = hp[lane + 32*k];
#pragma unroll
    for(int c=0;c<5;c++){
        float a = 0.f;
#pragma unroll
        for(int k=0;k<8;k++) a += hr[k] * w[(lane+32*k)*5 + c];
#pragma unroll
        for(int o=16;o;o>>=1) a += __shfl_xor_sync(0xffffffffu, a, o);
        if(lane==0) out[row*5 + c] = a + linb[c];
    }
}

// ------------------------------- host side -----------------------------------
extern "C" void kernel_launch(void* const* d_in, const int* in_sizes, int n_in,
                              void* d_out, int out_size){
    const int*   wordid = (const int*)  d_in[0];
    const int*   mask   = (const int*)  d_in[1];
    const float* emb    = (const float*)d_in[2];
    const float* q1w=(const float*)d_in[3],  *q1b=(const float*)d_in[4];
    const float* k1w=(const float*)d_in[5],  *k1b=(const float*)d_in[6];
    const float* v1w=(const float*)d_in[7],  *v1b=(const float*)d_in[8];
    const float* o1w=(const float*)d_in[9],  *o1b=(const float*)d_in[10];
    const float* q2w=(const float*)d_in[11], *q2b=(const float*)d_in[12];
    const float* k2w=(const float*)d_in[13], *k2b=(const float*)d_in[14];
    const float* v2w=(const float*)d_in[15], *v2b=(const float*)d_in[16];
    const float* o2w=(const float*)d_in[17], *o2b=(const float*)d_in[18];
    const float* ln1g=(const float*)d_in[19],*ln1bb=(const float*)d_in[20];
    const float* ln2g=(const float*)d_in[21],*ln2bb=(const float*)d_in[22];
    const float* linw=(const float*)d_in[23],*linb=(const float*)d_in[24];
    float* out = (float*)d_out;
    (void)k2b;  // uniform score shift -> softmax invariant

    float *H,*Ek,*Ev,*Hq,*Hk,*Hv,*state,*Sk,*Sv,*k2t,*ispart;
    __nv_bfloat16 *Hhi,*Hlo,*Ohi,*Olo,*Whi,*Wlo;
    cudaGetSymbolAddress((void**)&H,  g_H);
    cudaGetSymbolAddress((void**)&Ek, g_Ek);
    cudaGetSymbolAddress((void**)&Ev, g_Ev);
    cudaGetSymbolAddress((void**)&Hq, g_Hq);
    cudaGetSymbolAddress((void**)&Hk, g_Hk);
    cudaGetSymbolAddress((void**)&Hv, g_Hv);
    cudaGetSymbolAddress((void**)&state, g_state);
    cudaGetSymbolAddress((void**)&Sk, g_Sk);
    cudaGetSymbolAddress((void**)&Sv, g_Sv);
    cudaGetSymbolAddress((void**)&k2t, g_k2t);
    cudaGetSymbolAddress((void**)&ispart, g_ispart);
    cudaGetSymbolAddress((void**)&Hhi, g_Hhi);
    cudaGetSymbolAddress((void**)&Hlo, g_Hlo);
    cudaGetSymbolAddress((void**)&Ohi, g_Ohi);
    cudaGetSymbolAddress((void**)&Olo, g_Olo);
    cudaGetSymbolAddress((void**)&Whi, g_Whi);
    cudaGetSymbolAddress((void**)&Wlo, g_Wlo);

    cudaFuncSetAttribute(tcgemm3_kernel,        cudaFuncAttributeMaxDynamicSharedMemorySize, GEMM_SMEM);
    cudaFuncSetAttribute(tcgemm_ln_kernel,      cudaFuncAttributeMaxDynamicSharedMemorySize, GEMM_SMEM);
    cudaFuncSetAttribute(fused_qkv_step2_kernel,cudaFuncAttributeMaxDynamicSharedMemorySize, GEMM_SMEM);

    wsplit_kernel<<<dim3(DD*DD/256, 4), 256>>>(q1w, k1w, v1w, o1w, Whi, Wlo);
    trans_kernel <<<dim3(8,8), 256>>>(k2w, k2t);
    embed_kernel    <<<MR, 256>>>(wordid, mask, emb, H, Hhi, Hlo);
    initstate_part<<<dim3(BB,4), 256>>>(H, ispart);
    initstate_comb<<<BB, 256>>>(ispart, state);
    sgemm_kernel<<<dim3(4,2), 256>>>(state, k1w, k1b, Sk, v1w, v1b, Sv);

    // qkv for iteration 0 (h == e, so k1/v1 outputs double as loop-invariant Ek/Ev)
    tcgemm3_kernel<<<dim3(MT,3), 256, GEMM_SMEM>>>(Hhi, Hlo, Whi, Wlo,
                                                   q1b, k1b, v1b, Hq, Ek, Ev);

    for(int it = 0; it < 5; it++){
        const float* kBuf = (it == 0) ? Ek : Hk;
        const float* vBuf = (it == 0) ? Ev : Hv;
        attn1_kernel<<<MR/4, 256>>>(Hq, kBuf, vBuf, Ek, Ev, Sk, Sv, k1b, v1b, Ohi, Olo);
        tcgemm_ln_kernel<<<MT, 256, GEMM_SMEM>>>(Ohi, Olo, Whi + 3L*DD*DD, Wlo + 3L*DD*DD,
                                                 o1b, ln1g, ln1bb, H, Hhi, Hlo);
        if(it < 4){
            // step2(it) runs concurrently with qkv(it+1) in one launch;
            // step2 at it==4 would compute a state that is never read -> skipped.
            fused_qkv_step2_kernel<<<64 + 3*MT, 256, GEMM_SMEM>>>(
                Hhi, Hlo, Whi, Wlo, q1b, k1b, v1b, Hq, Hk, Hv,
                H, state, q2w, q2b, k2t, v2w, v2b, o2w, o2b,
                ln2g, ln2bb, k1w, v1w, Sk, Sv);
        }
    }

    logits_kernel<<<MR/8, 256>>>(H, linw, linb, out);
}